// round 11
// baseline (speedup 1.0000x reference)
#include <cuda_runtime.h>
#include <cuda_bf16.h>
#include <math.h>
#include <stdint.h>

// Problem constants
#define BB   64      // batch
#define SS   64      // encoder seq len
#define TT   32      // decoder target len
#define VV   32000   // vocab
#define EE   256     // embedding
#define HH   512     // hidden
#define H3   1536    // 3*H
#define GCTAS 16     // GRU grid (single wave, cheap 16-way barrier)

// ---------- device scratch (static; NEVER passed as kernel args from host) ----------
__device__ __align__(16) float          g_h[2][BB * HH];     // hidden fp32, double buffered
__device__ __align__(16) __nv_bfloat16  g_hb[2][BB * HH];    // hidden bf16, double buffered
__device__ __align__(16) float          g_z[BB * HH];        // sigmoid(z-gate)
__device__ __align__(16) __nv_bfloat16  g_rh[BB * HH];       // bf16(r * h)
__device__ __align__(16) __nv_bfloat16  g_xseq[SS * BB * EE];  // encoder x bf16 [s][b][k]
__device__ __align__(16) __nv_bfloat16  g_wxt[2][H3 * EE];   // Wx^T [col][k] bf16 (0=enc,1=dec)
__device__ __align__(16) __nv_bfloat16  g_wht[2][H3 * HH];   // Wh^T [col][k] bf16
__device__ __align__(16) __nv_bfloat16  g_wt[(size_t)VV * HH]; // fc_W^T [v][k] bf16
__device__ __align__(16) float          g_logits[(size_t)BB * VV];
__device__ float                        g_ce[BB];
__device__ int                          g_tok[BB];
__device__ unsigned                     g_bar;

__device__ __forceinline__ float sigf(float x) { return 1.0f / (1.0f + expf(-x)); }

// 16-CTA counting barrier: hot spin on one L2 line (proven round 9).
__device__ __forceinline__ void gbar(unsigned target) {
    __syncthreads();
    if (threadIdx.x == 0) {
        __threadfence();                   // release
        atomicAdd(&g_bar, 1u);
        volatile unsigned* vp = &g_bar;
        while (*vp < target) {}
    }
    __syncthreads();
    __threadfence();                       // acquire
}

// ---------- mma helpers (fragment layout proven in k_fc, rounds 4 & 9) ----------
__device__ __forceinline__ void mma16816(float* d, const uint32_t* a, const uint32_t* b) {
    asm volatile(
        "mma.sync.aligned.m16n8k16.row.col.f32.bf16.bf16.f32 "
        "{%0,%1,%2,%3},{%4,%5,%6,%7},{%8,%9},{%0,%1,%2,%3};\n"
        : "+f"(d[0]), "+f"(d[1]), "+f"(d[2]), "+f"(d[3])
        : "r"(a[0]), "r"(a[1]), "r"(a[2]), "r"(a[3]), "r"(b[0]), "r"(b[1]));
}
__device__ __forceinline__ void ldsm4(uint32_t* a, const void* p) {
    uint32_t saddr = (uint32_t)__cvta_generic_to_shared(p);
    asm volatile("ldmatrix.sync.aligned.m8n8.x4.shared.b16 {%0,%1,%2,%3},[%4];\n"
        : "=r"(a[0]), "=r"(a[1]), "=r"(a[2]), "=r"(a[3]) : "r"(saddr));
}

// -------------------- init --------------------
__global__ void k_init(float* out) {
    int b = blockIdx.x, t = threadIdx.x;
    g_h[0][b * HH + t] = 0.0f;
    g_hb[0][b * HH + t] = __float2bfloat16(0.0f);
    if (t == 0) g_tok[b] = 1;              // BEGIN token
    if (b == 0 && t == 0) { out[0] = 0.0f; g_bar = 0u; }
}

// -------- fc_W [k][v] fp32 -> g_wt [v][k] bf16 (internal dst; proven) --------
__global__ void k_prept(const float* __restrict__ fcW) {
    __shared__ float Ts[32][33];
    int v0 = blockIdx.x * 32, k0 = blockIdx.y * 32;
    int c = threadIdx.x & 31, r8 = threadIdx.x >> 5;
    #pragma unroll
    for (int i = 0; i < 4; i++) {
        int r = r8 + 8 * i;
        Ts[r][c] = fcW[(size_t)(k0 + r) * VV + v0 + c];
    }
    __syncthreads();
    #pragma unroll
    for (int i = 0; i < 4; i++) {
        int r = r8 + 8 * i;
        g_wt[(size_t)(v0 + r) * HH + k0 + c] = __float2bfloat16(Ts[c][r]);
    }
}

// -------- GRU weight transpose: fp32 [K][1536] -> bf16 [1536][K], dst selected INSIDE ----
// sel: 0=enc Wx, 1=enc Wh, 2=dec Wx, 3=dec Wh.  K = EE for Wx, HH for Wh.
__global__ void k_prepw(const float* __restrict__ src, int sel, int K) {
    __shared__ float Ts[32][33];
    __nv_bfloat16* dst = (sel == 0) ? g_wxt[0] : (sel == 1) ? g_wht[0]
                        : (sel == 2) ? g_wxt[1] : g_wht[1];
    int j0 = blockIdx.x * 32, k0 = blockIdx.y * 32;
    int c = threadIdx.x & 31, r8 = threadIdx.x >> 5;
    #pragma unroll
    for (int i = 0; i < 4; i++) {
        int r = r8 + 8 * i;
        Ts[r][c] = src[(size_t)(k0 + r) * H3 + j0 + c];
    }
    __syncthreads();
    #pragma unroll
    for (int i = 0; i < 4; i++) {
        int r = r8 + 8 * i;
        dst[(size_t)(j0 + r) * K + k0 + c] = __float2bfloat16(Ts[c][r]);
    }
}

// -------- encoder x pre-gather: bf16 [s][b][256] (internal dst) --------
__global__ void k_xseq(const int* __restrict__ inp, const float* __restrict__ emb) {
    int s = blockIdx.x, b = blockIdx.y, t = threadIdx.x;
    int row = inp[b * SS + s];
    g_xseq[((size_t)s * BB + b) * EE + t] = __float2bfloat16(emb[(size_t)row * EE + t]);
}

// -------------------- persistent tensor-core GRU (16 CTAs) --------------------
// Phase 1: zr GEMM (cols [0,1024), K=768 = x(256)+h(512)), 16 CTAs x 64 cols.
//   Epilogue: cols<512 -> z=sig;  cols in [512,1024) -> rh=bf16(sig * h).
// Phase 2: candidate GEMM (weight cols [1024,1536), K=768 = x+rh), 16 CTAs x 32 cols.
//   Epilogue: hh=tanh(.+b); h' = z*h + (1-z)*hh -> g_h/g_hb[dst].  2 barriers/step.
// xenc=1: x from g_xseq (steps sbase+s);  xenc=0: gather embd[g_tok] (decoder).
__global__ void __launch_bounds__(256) k_gru2(
        const float* __restrict__ embd,      // harness pointer (decoder) or nullptr
        const float* __restrict__ bias,      // harness pointer
        int wsel, int xenc, int src, int nsteps, int sbase, unsigned bar_base)
{
    __shared__ __align__(16) __nv_bfloat16 As[64][264];
    const __nv_bfloat16* wxt = g_wxt[wsel];
    const __nv_bfloat16* wht = g_wht[wsel];
    int bx = blockIdx.x, t = threadIdx.x;
    int warp = t >> 5, lane = t & 31;
    int g = lane >> 2, tig = lane & 3;
    int lr = lane & 7, sel = lane >> 3;
    int arow = lr + (sel & 1) * 8;
    int acol = (sel >> 1) * 8;
    int mt = warp & 3, nh = warp >> 2;      // 4 m-tiles x 2 n-halves
    unsigned nbar = bar_base;
    int cs = src;

    for (int s = 0; s < nsteps; s++) {
        // ================= Phase 1: zr GEMM =================
        int jb = bx * 64;
        float acc[4][4];
        #pragma unroll
        for (int n = 0; n < 4; n++) { acc[n][0]=0.f; acc[n][1]=0.f; acc[n][2]=0.f; acc[n][3]=0.f; }

        for (int c = 0; c < 3; c++) {
            __syncthreads();
            if (c == 0) {
                if (xenc) {
                    const uint4* sp = (const uint4*)(g_xseq + (size_t)(sbase + s) * BB * EE);
                    for (int l = t; l < 2048; l += 256) {
                        int row = l >> 5, ch = l & 31;
                        *(uint4*)&As[row][ch * 8] = sp[row * 32 + ch];
                    }
                } else {
                    for (int l = t; l < 4096; l += 256) {
                        int row = l >> 6, kk = (l & 63) * 4;
                        float4 v = *(const float4*)(embd + (size_t)g_tok[row] * EE + kk);
                        __nv_bfloat162* dp = (__nv_bfloat162*)&As[row][kk];
                        dp[0] = __floats2bfloat162_rn(v.x, v.y);
                        dp[1] = __floats2bfloat162_rn(v.z, v.w);
                    }
                }
            } else {
                const uint4* hp = (const uint4*)(g_hb[cs]);
                for (int l = t; l < 2048; l += 256) {
                    int row = l >> 5, ch = l & 31;
                    *(uint4*)&As[row][ch * 8] = __ldcg(&hp[row * 64 + (c - 1) * 32 + ch]);
                }
            }
            __syncthreads();

            const __nv_bfloat16* WT = (c == 0) ? wxt : wht;
            int Kd  = (c == 0) ? EE : HH;
            int kro = (c == 0) ? 0 : (c - 1) * 256;
            for (int ks = 0; ks < 16; ks++) {
                int kl = ks * 16;
                uint32_t afr[4];
                ldsm4(afr, &As[mt * 16 + arow][kl + acol]);
                #pragma unroll
                for (int nt = 0; nt < 4; nt++) {
                    const __nv_bfloat16* wr =
                        WT + (size_t)(jb + nh * 32 + nt * 8 + g) * Kd + kro + kl;
                    uint32_t bb[2];
                    bb[0] = *(const uint32_t*)(wr + 2 * tig);
                    bb[1] = *(const uint32_t*)(wr + 8 + 2 * tig);
                    mma16816(acc[nt], afr, bb);
                }
            }
        }

        // Phase 1 epilogue
        {
            bool isZ = (jb < 512);
            #pragma unroll
            for (int nt = 0; nt < 4; nt++) {
                int col = jb + nh * 32 + nt * 8 + 2 * tig;
                float b0 = bias[col], b1 = bias[col + 1];
                #pragma unroll
                for (int half = 0; half < 2; half++) {
                    int b = mt * 16 + g + half * 8;
                    float v0 = acc[nt][half * 2 + 0];
                    float v1 = acc[nt][half * 2 + 1];
                    if (isZ) {
                        *(float2*)&g_z[b * HH + col] = make_float2(sigf(v0 + b0), sigf(v1 + b1));
                    } else {
                        int cr = col - 512;
                        float2 hv = __ldcg((const float2*)&g_h[cs][b * HH + cr]);
                        __nv_bfloat162 o;
                        o.x = __float2bfloat16(sigf(v0 + b0) * hv.x);
                        o.y = __float2bfloat16(sigf(v1 + b1) * hv.y);
                        *(__nv_bfloat162*)&g_rh[b * HH + cr] = o;
                    }
                }
            }
        }
        nbar++; gbar(nbar * GCTAS);

        // ================= Phase 2: candidate GEMM (K=768: x then rh) =================
        int cj0 = bx * 32;
        float acc2[2][4];
        #pragma unroll
        for (int n = 0; n < 2; n++) { acc2[n][0]=0.f; acc2[n][1]=0.f; acc2[n][2]=0.f; acc2[n][3]=0.f; }

        for (int c = 0; c < 3; c++) {
            __syncthreads();
            if (c == 0) {
                if (xenc) {
                    const uint4* sp = (const uint4*)(g_xseq + (size_t)(sbase + s) * BB * EE);
                    for (int l = t; l < 2048; l += 256) {
                        int row = l >> 5, ch = l & 31;
                        *(uint4*)&As[row][ch * 8] = sp[row * 32 + ch];
                    }
                } else {
                    for (int l = t; l < 4096; l += 256) {
                        int row = l >> 6, kk = (l & 63) * 4;
                        float4 v = *(const float4*)(embd + (size_t)g_tok[row] * EE + kk);
                        __nv_bfloat162* dp = (__nv_bfloat162*)&As[row][kk];
                        dp[0] = __floats2bfloat162_rn(v.x, v.y);
                        dp[1] = __floats2bfloat162_rn(v.z, v.w);
                    }
                }
            } else {
                const uint4* rp = (const uint4*)g_rh;
                for (int l = t; l < 2048; l += 256) {
                    int row = l >> 5, ch = l & 31;
                    *(uint4*)&As[row][ch * 8] = __ldcg(&rp[row * 64 + (c - 1) * 32 + ch]);
                }
            }
            __syncthreads();

            const __nv_bfloat16* WT = (c == 0) ? wxt : wht;
            int Kd  = (c == 0) ? EE : HH;
            int kro = (c == 0) ? 0 : (c - 1) * 256;
            for (int ks = 0; ks < 16; ks++) {
                int kl = ks * 16;
                uint32_t afr[4];
                ldsm4(afr, &As[mt * 16 + arow][kl + acol]);
                #pragma unroll
                for (int nt = 0; nt < 2; nt++) {
                    const __nv_bfloat16* wr =
                        WT + (size_t)(1024 + cj0 + nh * 16 + nt * 8 + g) * Kd + kro + kl;
                    uint32_t bb[2];
                    bb[0] = *(const uint32_t*)(wr + 2 * tig);
                    bb[1] = *(const uint32_t*)(wr + 8 + 2 * tig);
                    mma16816(acc2[nt], afr, bb);
                }
            }
        }

        // Phase 2 epilogue: tanh + blend -> h'
        {
            int nd = cs ^ 1;
            #pragma unroll
            for (int nt = 0; nt < 2; nt++) {
                int cj = cj0 + nh * 16 + nt * 8 + 2 * tig;
                float b0 = bias[1024 + cj], b1 = bias[1024 + cj + 1];
                #pragma unroll
                for (int half = 0; half < 2; half++) {
                    int b = mt * 16 + g + half * 8;
                    float hh0 = tanhf(acc2[nt][half * 2 + 0] + b0);
                    float hh1 = tanhf(acc2[nt][half * 2 + 1] + b1);
                    float2 zv = __ldcg((const float2*)&g_z[b * HH + cj]);
                    float2 hv = __ldcg((const float2*)&g_h[cs][b * HH + cj]);
                    float hn0 = zv.x * hv.x + (1.0f - zv.x) * hh0;
                    float hn1 = zv.y * hv.y + (1.0f - zv.y) * hh1;
                    *(float2*)&g_h[nd][b * HH + cj] = make_float2(hn0, hn1);
                    __nv_bfloat162 ob;
                    ob.x = __float2bfloat16(hn0);
                    ob.y = __float2bfloat16(hn1);
                    *(__nv_bfloat162*)&g_hb[nd][b * HH + cj] = ob;
                }
            }
        }
        nbar++; gbar(nbar * GCTAS);
        cs ^= 1;
    }
}

// -------------------- tensor-core fc (proven; hb buffer selected internally) ------------
#define HS_STRIDE 264
__global__ void __launch_bounds__(256) k_fc(const float* __restrict__ fcb, int hsrc) {
    __shared__ __align__(16) __nv_bfloat16 Hs[64][HS_STRIDE];
    int t = threadIdx.x;
    int warp = t >> 5, lane = t & 31;
    int g = lane >> 2, tig = lane & 3;
    int vbase = blockIdx.x * 256 + warp * 32;

    float acc[4][4][4];
    #pragma unroll
    for (int m = 0; m < 4; m++)
        #pragma unroll
        for (int n = 0; n < 4; n++)
            { acc[m][n][0]=0.f; acc[m][n][1]=0.f; acc[m][n][2]=0.f; acc[m][n][3]=0.f; }

    int lr  = lane & 7;
    int sel = lane >> 3;
    int arow_off = lr + (sel & 1) * 8;
    int acol_off = (sel >> 1) * 8;

    for (int kh = 0; kh < 2; kh++) {
        int k0g = kh * 256;
        __syncthreads();
        for (int l = t; l < 2048; l += 256) {
            int row = l >> 5, ch = l & 31;
            const uint4* srcp = (const uint4*)(g_hb[hsrc] + row * HH + k0g);
            *(uint4*)&Hs[row][ch * 8] = srcp[ch];
        }
        __syncthreads();

        uint32_t bcur[4][2], bnxt[4][2];
        #pragma unroll
        for (int nt = 0; nt < 4; nt++) {
            const __nv_bfloat16* wr = g_wt + (size_t)(vbase + nt * 8 + g) * HH + k0g;
            bcur[nt][0] = *(const uint32_t*)(wr + 2 * tig);
            bcur[nt][1] = *(const uint32_t*)(wr + 8 + 2 * tig);
        }

        for (int ks = 0; ks < 16; ks++) {
            int kl = ks * 16;
            if (ks < 15) {
                int kn = kl + 16;
                #pragma unroll
                for (int nt = 0; nt < 4; nt++) {
                    const __nv_bfloat16* wr = g_wt + (size_t)(vbase + nt * 8 + g) * HH + k0g + kn;
                    bnxt[nt][0] = *(const uint32_t*)(wr + 2 * tig);
                    bnxt[nt][1] = *(const uint32_t*)(wr + 8 + 2 * tig);
                }
            }
            uint32_t afr[4][4];
            #pragma unroll
            for (int mt = 0; mt < 4; mt++)
                ldsm4(afr[mt], &Hs[mt * 16 + arow_off][kl + acol_off]);
            #pragma unroll
            for (int mt = 0; mt < 4; mt++)
                #pragma unroll
                for (int nt = 0; nt < 4; nt++)
                    mma16816(acc[mt][nt], afr[mt], bcur[nt]);
            if (ks < 15) {
                #pragma unroll
                for (int nt = 0; nt < 4; nt++) { bcur[nt][0] = bnxt[nt][0]; bcur[nt][1] = bnxt[nt][1]; }
            }
        }
    }

    #pragma unroll
    for (int nt = 0; nt < 4; nt++) {
        int col = vbase + nt * 8 + 2 * tig;
        float2 bv = *(const float2*)(fcb + col);
        #pragma unroll
        for (int mt = 0; mt < 4; mt++) {
            int r0 = mt * 16 + g;
            float2 o0 = make_float2(acc[mt][nt][0] + bv.x, acc[mt][nt][1] + bv.y);
            float2 o1 = make_float2(acc[mt][nt][2] + bv.x, acc[mt][nt][3] + bv.y);
            *(float2*)&g_logits[(size_t)r0 * VV + col]       = o0;
            *(float2*)&g_logits[(size_t)(r0 + 8) * VV + col] = o1;
        }
    }
}

// -------------------- per-batch loss + argmax (proven) --------------------
__global__ void k_loss(const int* __restrict__ targ, int tcol) {
    __shared__ float sred[256];
    __shared__ float mred[256];
    __shared__ int   ired[256];
    int b = blockIdx.x, t = threadIdx.x;
    const float* lg = g_logits + (size_t)b * VV;

    float m = -3.4e38f; int mi = 0; float s1 = 0.f;
    for (int v = t; v < VV; v += 256) {
        float l = lg[v];
        s1 += expf(l);
        if (l > m) { m = l; mi = v; }
    }
    mred[t] = m; ired[t] = mi; sred[t] = s1;
    __syncthreads();
    for (int off = 128; off; off >>= 1) {
        if (t < off) {
            float mo = mred[t + off]; int io = ired[t + off];
            if (mo > mred[t] || (mo == mred[t] && io < ired[t])) { mred[t] = mo; ired[t] = io; }
            sred[t] += sred[t + off];
        }
        __syncthreads();
    }
    float inv_s1 = 1.0f / sred[0];
    int argmax = ired[0];
    __syncthreads();

    float s2 = 0.f;
    for (int v = t; v < VV; v += 256)
        s2 += expf(expf(lg[v]) * inv_s1);
    sred[t] = s2;
    __syncthreads();
    for (int off = 128; off; off >>= 1) {
        if (t < off) sred[t] += sred[t + off];
        __syncthreads();
    }
    if (t == 0) {
        int tgt = targ[b * TT + tcol];
        float pt = expf(lg[tgt]) * inv_s1;
        g_ce[b] = logf(sred[0]) - pt;
        g_tok[b] = argmax;
    }
}

// -------------------- deterministic masked-mean accumulate --------------------
__global__ void k_losssum(const int* __restrict__ targ, int tcol, float* out) {
    int t = threadIdx.x;  // 32
    float a = g_ce[t]      * ((targ[t * TT + tcol]        != 0) ? 1.f : 0.f);
    float c = g_ce[t + 32] * ((targ[(t + 32) * TT + tcol] != 0) ? 1.f : 0.f);
    float v = a + c;
    #pragma unroll
    for (int off = 16; off; off >>= 1)
        v += __shfl_down_sync(0xffffffffu, v, off);
    if (t == 0) out[0] += v * (1.0f / 64.0f);
}

// -------------------- launch (NO device-global addresses cross this boundary) -----------
extern "C" void kernel_launch(void* const* d_in, const int* in_sizes, int n_in,
                              void* d_out, int out_size)
{
    const int*   inp     = (const int*)  d_in[0];
    const int*   targ    = (const int*)  d_in[1];
    const float* emb_enc = (const float*)d_in[2];
    const float* enc_Wx  = (const float*)d_in[3];
    const float* enc_Wh  = (const float*)d_in[4];
    const float* enc_b   = (const float*)d_in[5];
    const float* emb_dec = (const float*)d_in[6];
    const float* dec_Wx  = (const float*)d_in[7];
    const float* dec_Wh  = (const float*)d_in[8];
    const float* dec_b   = (const float*)d_in[9];
    const float* fc_W    = (const float*)d_in[10];
    const float* fc_b    = (const float*)d_in[11];
    float* out = (float*)d_out;

    k_init<<<BB, HH>>>(out);
    k_prept<<<dim3(1000, 16), 256>>>(fc_W);
    k_prepw<<<dim3(48, 8),  256>>>(enc_Wx, 0, EE);
    k_prepw<<<dim3(48, 16), 256>>>(enc_Wh, 1, HH);
    k_prepw<<<dim3(48, 8),  256>>>(dec_Wx, 2, EE);
    k_prepw<<<dim3(48, 16), 256>>>(dec_Wh, 3, HH);
    k_xseq<<<dim3(SS, BB), EE>>>(inp, emb_enc);

    unsigned barb = 0;
    // encoder: 64 GRU steps, ONE launch
    k_gru2<<<GCTAS, 256>>>(nullptr, enc_b, 0, 1, 0, SS, 0, barb);
    barb += 2 * SS;

    int src = 0;   // SS even -> final encoder state in buffer 0
    for (int tt = 1; tt < TT; tt++) {
        k_gru2<<<GCTAS, 256>>>(emb_dec, dec_b, 1, 0, src, 1, 0, barb);
        barb += 2;
        src ^= 1;
        k_fc<<<125, 256>>>(fc_b, src);
        k_loss<<<BB, 256>>>(targ, tt);
        k_losssum<<<1, 32>>>(targ, tt, out);
    }
}

// round 12
// speedup vs baseline: 1.2487x; 1.2487x over previous
#include <cuda_runtime.h>
#include <cuda_bf16.h>
#include <math.h>
#include <stdint.h>

// Problem constants
#define BB   64      // batch
#define SS   64      // encoder seq len
#define TT   32      // decoder target len
#define VV   32000   // vocab
#define EE   256     // embedding
#define HH   512     // hidden
#define H3   1536    // 3*H
#define GCTAS 32     // GRU grid (single wave, cheap 32-way barrier)

// ---------- device scratch (static; NEVER passed as kernel args from host) ----------
__device__ __align__(16) float          g_h[2][BB * HH];     // hidden fp32, double buffered
__device__ __align__(16) __nv_bfloat16  g_hb[2][BB * HH];    // hidden bf16, double buffered
__device__ __align__(16) float          g_z[BB * HH];        // sigmoid(z-gate)
__device__ __align__(16) __nv_bfloat16  g_rh[BB * HH];       // bf16(r * h)
__device__ __align__(16) __nv_bfloat16  g_xseq[SS * BB * EE];  // encoder x bf16 [s][b][k]
__device__ __align__(16) __nv_bfloat16  g_wxt[2][H3 * EE];   // Wx^T [col][k] bf16 (0=enc,1=dec)
__device__ __align__(16) __nv_bfloat16  g_wht[2][H3 * HH];   // Wh^T [col][k] bf16
__device__ __align__(16) __nv_bfloat16  g_wt[(size_t)VV * HH]; // fc_W^T [v][k] bf16
__device__ __align__(16) float          g_logits[(size_t)BB * VV];
__device__ int                          g_tok[BB];
__device__ unsigned                     g_bar;

__device__ __forceinline__ float sigf(float x) { return 1.0f / (1.0f + expf(-x)); }

// 32-CTA counting barrier: hot spin on one L2 line.
__device__ __forceinline__ void gbar(unsigned target) {
    __syncthreads();
    if (threadIdx.x == 0) {
        __threadfence();                   // release
        atomicAdd(&g_bar, 1u);
        volatile unsigned* vp = &g_bar;
        while (*vp < target) {}
    }
    __syncthreads();
    __threadfence();                       // acquire
}

// ---------- mma helpers (fragment layout proven in k_fc, rounds 4/9/11) ----------
__device__ __forceinline__ void mma16816(float* d, const uint32_t* a, const uint32_t* b) {
    asm volatile(
        "mma.sync.aligned.m16n8k16.row.col.f32.bf16.bf16.f32 "
        "{%0,%1,%2,%3},{%4,%5,%6,%7},{%8,%9},{%0,%1,%2,%3};\n"
        : "+f"(d[0]), "+f"(d[1]), "+f"(d[2]), "+f"(d[3])
        : "r"(a[0]), "r"(a[1]), "r"(a[2]), "r"(a[3]), "r"(b[0]), "r"(b[1]));
}
__device__ __forceinline__ void ldsm4(uint32_t* a, const void* p) {
    uint32_t saddr = (uint32_t)__cvta_generic_to_shared(p);
    asm volatile("ldmatrix.sync.aligned.m8n8.x4.shared.b16 {%0,%1,%2,%3},[%4];\n"
        : "=r"(a[0]), "=r"(a[1]), "=r"(a[2]), "=r"(a[3]) : "r"(saddr));
}

// -------------------- init --------------------
__global__ void k_init(float* out) {
    int b = blockIdx.x, t = threadIdx.x;
    g_h[0][b * HH + t] = 0.0f;
    g_hb[0][b * HH + t] = __float2bfloat16(0.0f);
    if (t == 0) g_tok[b] = 1;              // BEGIN token
    if (b == 0 && t == 0) { out[0] = 0.0f; g_bar = 0u; }
}

// -------- fc_W [k][v] fp32 -> g_wt [v][k] bf16 (internal dst; proven) --------
__global__ void k_prept(const float* __restrict__ fcW) {
    __shared__ float Ts[32][33];
    int v0 = blockIdx.x * 32, k0 = blockIdx.y * 32;
    int c = threadIdx.x & 31, r8 = threadIdx.x >> 5;
    #pragma unroll
    for (int i = 0; i < 4; i++) {
        int r = r8 + 8 * i;
        Ts[r][c] = fcW[(size_t)(k0 + r) * VV + v0 + c];
    }
    __syncthreads();
    #pragma unroll
    for (int i = 0; i < 4; i++) {
        int r = r8 + 8 * i;
        g_wt[(size_t)(v0 + r) * HH + k0 + c] = __float2bfloat16(Ts[c][r]);
    }
}

// -------- GRU weight transpose: fp32 [K][1536] -> bf16 [1536][K], dst selected INSIDE ----
__global__ void k_prepw(const float* __restrict__ src, int sel, int K) {
    __shared__ float Ts[32][33];
    __nv_bfloat16* dst = (sel == 0) ? g_wxt[0] : (sel == 1) ? g_wht[0]
                        : (sel == 2) ? g_wxt[1] : g_wht[1];
    int j0 = blockIdx.x * 32, k0 = blockIdx.y * 32;
    int c = threadIdx.x & 31, r8 = threadIdx.x >> 5;
    #pragma unroll
    for (int i = 0; i < 4; i++) {
        int r = r8 + 8 * i;
        Ts[r][c] = src[(size_t)(k0 + r) * H3 + j0 + c];
    }
    __syncthreads();
    #pragma unroll
    for (int i = 0; i < 4; i++) {
        int r = r8 + 8 * i;
        dst[(size_t)(j0 + r) * K + k0 + c] = __float2bfloat16(Ts[c][r]);
    }
}

// -------- encoder x pre-gather: bf16 [s][b][256] (internal dst) --------
__global__ void k_xseq(const int* __restrict__ inp, const float* __restrict__ emb) {
    int s = blockIdx.x, b = blockIdx.y, t = threadIdx.x;
    int row = inp[b * SS + s];
    g_xseq[((size_t)s * BB + b) * EE + t] = __float2bfloat16(emb[(size_t)row * EE + t]);
}

// -------------------- persistent tensor-core GRU (32 CTAs) --------------------
// Phase 1: zr GEMM (cols [0,1024), K=768 = x(256)+h(512)), 32 CTAs x 32 cols.
//   Epilogue: cols<512 -> z=sig;  cols in [512,1024) -> rh=bf16(sig * h).
// Phase 2: candidate GEMM (weight cols [1024,1536), K=768 = x+rh), 32 CTAs x 16 cols.
//   Epilogue: hh=tanh(.+b); h' = z*h + (1-z)*hh.      2 barriers/step.
// B fragments double-buffered inside every ks-loop (k_fc pattern).
__global__ void __launch_bounds__(256) k_gru2(
        const float* __restrict__ embd,      // harness pointer (decoder) or nullptr
        const float* __restrict__ bias,      // harness pointer
        int wsel, int xenc, int src, int nsteps, int sbase, unsigned bar_base)
{
    __shared__ __align__(16) __nv_bfloat16 As[64][264];
    const __nv_bfloat16* wxt = g_wxt[wsel];
    const __nv_bfloat16* wht = g_wht[wsel];
    int bx = blockIdx.x, t = threadIdx.x;
    int warp = t >> 5, lane = t & 31;
    int g = lane >> 2, tig = lane & 3;
    int lr = lane & 7, sel = lane >> 3;
    int arow = lr + (sel & 1) * 8;
    int acol = (sel >> 1) * 8;
    int mt = warp & 3, nh = warp >> 2;      // 4 m-tiles x 2 n-halves
    unsigned nbar = bar_base;
    int cs = src;

    for (int s = 0; s < nsteps; s++) {
        // ================= Phase 1: zr GEMM (32 cols/CTA) =================
        int jb = bx * 32;
        float acc[2][4];
        #pragma unroll
        for (int n = 0; n < 2; n++) { acc[n][0]=0.f; acc[n][1]=0.f; acc[n][2]=0.f; acc[n][3]=0.f; }

        for (int c = 0; c < 3; c++) {
            __syncthreads();
            if (c == 0) {
                if (xenc) {
                    const uint4* sp = (const uint4*)(g_xseq + (size_t)(sbase + s) * BB * EE);
                    for (int l = t; l < 2048; l += 256) {
                        int row = l >> 5, ch = l & 31;
                        *(uint4*)&As[row][ch * 8] = sp[row * 32 + ch];
                    }
                } else {
                    for (int l = t; l < 4096; l += 256) {
                        int row = l >> 6, kk = (l & 63) * 4;
                        float4 v = *(const float4*)(embd + (size_t)g_tok[row] * EE + kk);
                        __nv_bfloat162* dp = (__nv_bfloat162*)&As[row][kk];
                        dp[0] = __floats2bfloat162_rn(v.x, v.y);
                        dp[1] = __floats2bfloat162_rn(v.z, v.w);
                    }
                }
            } else {
                const uint4* hp = (const uint4*)(g_hb[cs]);
                for (int l = t; l < 2048; l += 256) {
                    int row = l >> 5, ch = l & 31;
                    *(uint4*)&As[row][ch * 8] = __ldcg(&hp[row * 64 + (c - 1) * 32 + ch]);
                }
            }
            __syncthreads();

            const __nv_bfloat16* WT = (c == 0) ? wxt : wht;
            int Kd  = (c == 0) ? EE : HH;
            int kro = (c == 0) ? 0 : (c - 1) * 256;

            uint32_t bcur[2][2], bnxt[2][2];
            #pragma unroll
            for (int nt = 0; nt < 2; nt++) {
                const __nv_bfloat16* wr =
                    WT + (size_t)(jb + nh * 16 + nt * 8 + g) * Kd + kro;
                bcur[nt][0] = *(const uint32_t*)(wr + 2 * tig);
                bcur[nt][1] = *(const uint32_t*)(wr + 8 + 2 * tig);
            }
            for (int ks = 0; ks < 16; ks++) {
                int kl = ks * 16;
                if (ks < 15) {
                    #pragma unroll
                    for (int nt = 0; nt < 2; nt++) {
                        const __nv_bfloat16* wr =
                            WT + (size_t)(jb + nh * 16 + nt * 8 + g) * Kd + kro + kl + 16;
                        bnxt[nt][0] = *(const uint32_t*)(wr + 2 * tig);
                        bnxt[nt][1] = *(const uint32_t*)(wr + 8 + 2 * tig);
                    }
                }
                uint32_t afr[4];
                ldsm4(afr, &As[mt * 16 + arow][kl + acol]);
                mma16816(acc[0], afr, bcur[0]);
                mma16816(acc[1], afr, bcur[1]);
                if (ks < 15) {
                    #pragma unroll
                    for (int nt = 0; nt < 2; nt++) { bcur[nt][0] = bnxt[nt][0]; bcur[nt][1] = bnxt[nt][1]; }
                }
            }
        }

        // Phase 1 epilogue
        {
            bool isZ = (jb < 512);
            #pragma unroll
            for (int nt = 0; nt < 2; nt++) {
                int col = jb + nh * 16 + nt * 8 + 2 * tig;
                float b0 = bias[col], b1 = bias[col + 1];
                #pragma unroll
                for (int half = 0; half < 2; half++) {
                    int b = mt * 16 + g + half * 8;
                    float v0 = acc[nt][half * 2 + 0];
                    float v1 = acc[nt][half * 2 + 1];
                    if (isZ) {
                        *(float2*)&g_z[b * HH + col] = make_float2(sigf(v0 + b0), sigf(v1 + b1));
                    } else {
                        int cr = col - 512;
                        float2 hv = __ldcg((const float2*)&g_h[cs][b * HH + cr]);
                        __nv_bfloat162 o;
                        o.x = __float2bfloat16(sigf(v0 + b0) * hv.x);
                        o.y = __float2bfloat16(sigf(v1 + b1) * hv.y);
                        *(__nv_bfloat162*)&g_rh[b * HH + cr] = o;
                    }
                }
            }
        }
        nbar++; gbar(nbar * GCTAS);

        // ================= Phase 2: candidate GEMM (16 cols/CTA, K=768) =================
        int cj0 = bx * 16;
        float acc2[4];
        acc2[0] = 0.f; acc2[1] = 0.f; acc2[2] = 0.f; acc2[3] = 0.f;

        for (int c = 0; c < 3; c++) {
            __syncthreads();
            if (c == 0) {
                if (xenc) {
                    const uint4* sp = (const uint4*)(g_xseq + (size_t)(sbase + s) * BB * EE);
                    for (int l = t; l < 2048; l += 256) {
                        int row = l >> 5, ch = l & 31;
                        *(uint4*)&As[row][ch * 8] = sp[row * 32 + ch];
                    }
                } else {
                    for (int l = t; l < 4096; l += 256) {
                        int row = l >> 6, kk = (l & 63) * 4;
                        float4 v = *(const float4*)(embd + (size_t)g_tok[row] * EE + kk);
                        __nv_bfloat162* dp = (__nv_bfloat162*)&As[row][kk];
                        dp[0] = __floats2bfloat162_rn(v.x, v.y);
                        dp[1] = __floats2bfloat162_rn(v.z, v.w);
                    }
                }
            } else {
                const uint4* rp = (const uint4*)g_rh;
                for (int l = t; l < 2048; l += 256) {
                    int row = l >> 5, ch = l & 31;
                    *(uint4*)&As[row][ch * 8] = __ldcg(&rp[row * 64 + (c - 1) * 32 + ch]);
                }
            }
            __syncthreads();

            const __nv_bfloat16* WT = (c == 0) ? wxt : wht;
            int Kd  = (c == 0) ? EE : HH;
            int kro = (c == 0) ? 0 : (c - 1) * 256;

            const __nv_bfloat16* wrow =
                WT + (size_t)(1024 + cj0 + nh * 8 + g) * Kd + kro;
            uint32_t bcur[2], bnxt[2];
            bcur[0] = *(const uint32_t*)(wrow + 2 * tig);
            bcur[1] = *(const uint32_t*)(wrow + 8 + 2 * tig);
            for (int ks = 0; ks < 16; ks++) {
                int kl = ks * 16;
                if (ks < 15) {
                    bnxt[0] = *(const uint32_t*)(wrow + kl + 16 + 2 * tig);
                    bnxt[1] = *(const uint32_t*)(wrow + kl + 16 + 8 + 2 * tig);
                }
                uint32_t afr[4];
                ldsm4(afr, &As[mt * 16 + arow][kl + acol]);
                mma16816(acc2, afr, bcur);
                if (ks < 15) { bcur[0] = bnxt[0]; bcur[1] = bnxt[1]; }
            }
        }

        // Phase 2 epilogue: tanh + blend -> h'
        {
            int nd = cs ^ 1;
            int cj = cj0 + nh * 8 + 2 * tig;
            float b0 = bias[1024 + cj], b1 = bias[1024 + cj + 1];
            #pragma unroll
            for (int half = 0; half < 2; half++) {
                int b = mt * 16 + g + half * 8;
                float hh0 = tanhf(acc2[half * 2 + 0] + b0);
                float hh1 = tanhf(acc2[half * 2 + 1] + b1);
                float2 zv = __ldcg((const float2*)&g_z[b * HH + cj]);
                float2 hv = __ldcg((const float2*)&g_h[cs][b * HH + cj]);
                float hn0 = zv.x * hv.x + (1.0f - zv.x) * hh0;
                float hn1 = zv.y * hv.y + (1.0f - zv.y) * hh1;
                *(float2*)&g_h[nd][b * HH + cj] = make_float2(hn0, hn1);
                __nv_bfloat162 ob;
                ob.x = __float2bfloat16(hn0);
                ob.y = __float2bfloat16(hn1);
                *(__nv_bfloat162*)&g_hb[nd][b * HH + cj] = ob;
            }
        }
        nbar++; gbar(nbar * GCTAS);
        cs ^= 1;
    }
}

// -------------------- tensor-core fc (proven) --------------------
#define HS_STRIDE 264
__global__ void __launch_bounds__(256) k_fc(const float* __restrict__ fcb, int hsrc) {
    __shared__ __align__(16) __nv_bfloat16 Hs[64][HS_STRIDE];
    int t = threadIdx.x;
    int warp = t >> 5, lane = t & 31;
    int g = lane >> 2, tig = lane & 3;
    int vbase = blockIdx.x * 256 + warp * 32;

    float acc[4][4][4];
    #pragma unroll
    for (int m = 0; m < 4; m++)
        #pragma unroll
        for (int n = 0; n < 4; n++)
            { acc[m][n][0]=0.f; acc[m][n][1]=0.f; acc[m][n][2]=0.f; acc[m][n][3]=0.f; }

    int lr  = lane & 7;
    int sel = lane >> 3;
    int arow_off = lr + (sel & 1) * 8;
    int acol_off = (sel >> 1) * 8;

    for (int kh = 0; kh < 2; kh++) {
        int k0g = kh * 256;
        __syncthreads();
        for (int l = t; l < 2048; l += 256) {
            int row = l >> 5, ch = l & 31;
            const uint4* srcp = (const uint4*)(g_hb[hsrc] + row * HH + k0g);
            *(uint4*)&Hs[row][ch * 8] = srcp[ch];
        }
        __syncthreads();

        uint32_t bcur[4][2], bnxt[4][2];
        #pragma unroll
        for (int nt = 0; nt < 4; nt++) {
            const __nv_bfloat16* wr = g_wt + (size_t)(vbase + nt * 8 + g) * HH + k0g;
            bcur[nt][0] = *(const uint32_t*)(wr + 2 * tig);
            bcur[nt][1] = *(const uint32_t*)(wr + 8 + 2 * tig);
        }

        for (int ks = 0; ks < 16; ks++) {
            int kl = ks * 16;
            if (ks < 15) {
                int kn = kl + 16;
                #pragma unroll
                for (int nt = 0; nt < 4; nt++) {
                    const __nv_bfloat16* wr = g_wt + (size_t)(vbase + nt * 8 + g) * HH + k0g + kn;
                    bnxt[nt][0] = *(const uint32_t*)(wr + 2 * tig);
                    bnxt[nt][1] = *(const uint32_t*)(wr + 8 + 2 * tig);
                }
            }
            uint32_t afr[4][4];
            #pragma unroll
            for (int mt = 0; mt < 4; mt++)
                ldsm4(afr[mt], &Hs[mt * 16 + arow_off][kl + acol_off]);
            #pragma unroll
            for (int mt = 0; mt < 4; mt++)
                #pragma unroll
                for (int nt = 0; nt < 4; nt++)
                    mma16816(acc[mt][nt], afr[mt], bcur[nt]);
            if (ks < 15) {
                #pragma unroll
                for (int nt = 0; nt < 4; nt++) { bcur[nt][0] = bnxt[nt][0]; bcur[nt][1] = bnxt[nt][1]; }
            }
        }
    }

    #pragma unroll
    for (int nt = 0; nt < 4; nt++) {
        int col = vbase + nt * 8 + 2 * tig;
        float2 bv = *(const float2*)(fcb + col);
        #pragma unroll
        for (int mt = 0; mt < 4; mt++) {
            int r0 = mt * 16 + g;
            float2 o0 = make_float2(acc[mt][nt][0] + bv.x, acc[mt][nt][1] + bv.y);
            float2 o1 = make_float2(acc[mt][nt][2] + bv.x, acc[mt][nt][3] + bv.y);
            *(float2*)&g_logits[(size_t)r0 * VV + col]       = o0;
            *(float2*)&g_logits[(size_t)(r0 + 8) * VV + col] = o1;
        }
    }
}

// -------------------- per-batch loss + argmax + fused masked-mean accumulate ------------
__global__ void k_loss(const int* __restrict__ targ, int tcol, float* __restrict__ out) {
    __shared__ float sred[256];
    __shared__ float mred[256];
    __shared__ int   ired[256];
    int b = blockIdx.x, t = threadIdx.x;
    const float* lg = g_logits + (size_t)b * VV;

    float m = -3.4e38f; int mi = 0; float s1 = 0.f;
    for (int v = t; v < VV; v += 256) {
        float l = lg[v];
        s1 += expf(l);
        if (l > m) { m = l; mi = v; }
    }
    mred[t] = m; ired[t] = mi; sred[t] = s1;
    __syncthreads();
    for (int off = 128; off; off >>= 1) {
        if (t < off) {
            float mo = mred[t + off]; int io = ired[t + off];
            if (mo > mred[t] || (mo == mred[t] && io < ired[t])) { mred[t] = mo; ired[t] = io; }
            sred[t] += sred[t + off];
        }
        __syncthreads();
    }
    float inv_s1 = 1.0f / sred[0];
    int argmax = ired[0];
    __syncthreads();

    float s2 = 0.f;
    for (int v = t; v < VV; v += 256)
        s2 += expf(expf(lg[v]) * inv_s1);
    sred[t] = s2;
    __syncthreads();
    for (int off = 128; off; off >>= 1) {
        if (t < off) sred[t] += sred[t + off];
        __syncthreads();
    }
    if (t == 0) {
        int tgt = targ[b * TT + tcol];
        float pt = expf(lg[tgt]) * inv_s1;
        float ce = logf(sred[0]) - pt;
        float mask = (tgt != 0) ? 1.0f : 0.0f;
        atomicAdd(out, ce * mask * (1.0f / 64.0f));
        g_tok[b] = argmax;
    }
}

// -------------------- launch (NO device-global addresses cross this boundary) -----------
extern "C" void kernel_launch(void* const* d_in, const int* in_sizes, int n_in,
                              void* d_out, int out_size)
{
    const int*   inp     = (const int*)  d_in[0];
    const int*   targ    = (const int*)  d_in[1];
    const float* emb_enc = (const float*)d_in[2];
    const float* enc_Wx  = (const float*)d_in[3];
    const float* enc_Wh  = (const float*)d_in[4];
    const float* enc_b   = (const float*)d_in[5];
    const float* emb_dec = (const float*)d_in[6];
    const float* dec_Wx  = (const float*)d_in[7];
    const float* dec_Wh  = (const float*)d_in[8];
    const float* dec_b   = (const float*)d_in[9];
    const float* fc_W    = (const float*)d_in[10];
    const float* fc_b    = (const float*)d_in[11];
    float* out = (float*)d_out;

    k_init<<<BB, HH>>>(out);
    k_prept<<<dim3(1000, 16), 256>>>(fc_W);
    k_prepw<<<dim3(48, 8),  256>>>(enc_Wx, 0, EE);
    k_prepw<<<dim3(48, 16), 256>>>(enc_Wh, 1, HH);
    k_prepw<<<dim3(48, 8),  256>>>(dec_Wx, 2, EE);
    k_prepw<<<dim3(48, 16), 256>>>(dec_Wh, 3, HH);
    k_xseq<<<dim3(SS, BB), EE>>>(inp, emb_enc);

    unsigned barb = 0;
    // encoder: 64 GRU steps, ONE launch
    k_gru2<<<GCTAS, 256>>>(nullptr, enc_b, 0, 1, 0, SS, 0, barb);
    barb += 2 * SS;

    int src = 0;   // SS even -> final encoder state in buffer 0
    for (int tt = 1; tt < TT; tt++) {
        k_gru2<<<GCTAS, 256>>>(emb_dec, dec_b, 1, 0, src, 1, 0, barb);
        barb += 2;
        src ^= 1;
        k_fc<<<125, 256>>>(fc_b, src);
        k_loss<<<BB, 256>>>(targ, tt, out);
    }
}

// round 13
// speedup vs baseline: 1.4306x; 1.1457x over previous
#include <cuda_runtime.h>
#include <cuda_bf16.h>
#include <math.h>
#include <stdint.h>

// Problem constants
#define BB   64      // batch
#define SS   64      // encoder seq len
#define TT   32      // decoder target len
#define VV   32000   // vocab
#define EE   256     // embedding
#define HH   512     // hidden
#define H3   1536    // 3*H
#define GCTAS 32     // GRU grid (single wave, cheap 32-way barrier)

// ---------- device scratch (static; NEVER passed as kernel args from host) ----------
__device__ __align__(16) float          g_h[2][BB * HH];     // hidden fp32, double buffered
__device__ __align__(16) __nv_bfloat16  g_hb[2][BB * HH];    // hidden bf16, double buffered
__device__ __align__(16) float          g_z[BB * HH];        // sigmoid(z-gate)
__device__ __align__(16) __nv_bfloat16  g_rh[BB * HH];       // bf16(r * h)
__device__ __align__(16) __nv_bfloat16  g_xseq[SS * BB * EE];  // encoder x bf16 [s][b][k]
__device__ __align__(16) __nv_bfloat16  g_wxt[2][H3 * EE];   // Wx^T [col][k] bf16 (0=enc,1=dec)
__device__ __align__(16) __nv_bfloat16  g_wht[2][H3 * HH];   // Wh^T [col][k] bf16
__device__ __align__(16) __nv_bfloat16  g_wt[(size_t)VV * HH]; // fc_W^T [v][k] bf16
__device__ __align__(16) float          g_logits[(size_t)BB * VV];
__device__ int                          g_tok[BB];
__device__ unsigned                     g_bar;

__device__ __forceinline__ float sigf(float x) { return 1.0f / (1.0f + expf(-x)); }

// 32-CTA counting barrier: hot spin on one L2 line.
__device__ __forceinline__ void gbar(unsigned target) {
    __syncthreads();
    if (threadIdx.x == 0) {
        __threadfence();                   // release
        atomicAdd(&g_bar, 1u);
        volatile unsigned* vp = &g_bar;
        while (*vp < target) {}
    }
    __syncthreads();
    __threadfence();                       // acquire
}

// ---------- mma helpers (fragment layout proven in k_fc, rounds 4/9/11/12) ----------
__device__ __forceinline__ void mma16816(float* d, const uint32_t* a, const uint32_t* b) {
    asm volatile(
        "mma.sync.aligned.m16n8k16.row.col.f32.bf16.bf16.f32 "
        "{%0,%1,%2,%3},{%4,%5,%6,%7},{%8,%9},{%0,%1,%2,%3};\n"
        : "+f"(d[0]), "+f"(d[1]), "+f"(d[2]), "+f"(d[3])
        : "r"(a[0]), "r"(a[1]), "r"(a[2]), "r"(a[3]), "r"(b[0]), "r"(b[1]));
}
__device__ __forceinline__ void ldsm4(uint32_t* a, const void* p) {
    uint32_t saddr = (uint32_t)__cvta_generic_to_shared(p);
    asm volatile("ldmatrix.sync.aligned.m8n8.x4.shared.b16 {%0,%1,%2,%3},[%4];\n"
        : "=r"(a[0]), "=r"(a[1]), "=r"(a[2]), "=r"(a[3]) : "r"(saddr));
}

// -------------------- init --------------------
__global__ void k_init(float* out) {
    int b = blockIdx.x, t = threadIdx.x;
    g_h[0][b * HH + t] = 0.0f;
    g_hb[0][b * HH + t] = __float2bfloat16(0.0f);
    if (t == 0) g_tok[b] = 1;              // BEGIN token
    if (b == 0 && t == 0) { out[0] = 0.0f; g_bar = 0u; }
}

// -------- fc_W [k][v] fp32 -> g_wt [v][k] bf16 (internal dst; proven) --------
__global__ void k_prept(const float* __restrict__ fcW) {
    __shared__ float Ts[32][33];
    int v0 = blockIdx.x * 32, k0 = blockIdx.y * 32;
    int c = threadIdx.x & 31, r8 = threadIdx.x >> 5;
    #pragma unroll
    for (int i = 0; i < 4; i++) {
        int r = r8 + 8 * i;
        Ts[r][c] = fcW[(size_t)(k0 + r) * VV + v0 + c];
    }
    __syncthreads();
    #pragma unroll
    for (int i = 0; i < 4; i++) {
        int r = r8 + 8 * i;
        g_wt[(size_t)(v0 + r) * HH + k0 + c] = __float2bfloat16(Ts[c][r]);
    }
}

// -------- GRU weight transpose: fp32 [K][1536] -> bf16 [1536][K], dst selected INSIDE ----
__global__ void k_prepw(const float* __restrict__ src, int sel, int K) {
    __shared__ float Ts[32][33];
    __nv_bfloat16* dst = (sel == 0) ? g_wxt[0] : (sel == 1) ? g_wht[0]
                        : (sel == 2) ? g_wxt[1] : g_wht[1];
    int j0 = blockIdx.x * 32, k0 = blockIdx.y * 32;
    int c = threadIdx.x & 31, r8 = threadIdx.x >> 5;
    #pragma unroll
    for (int i = 0; i < 4; i++) {
        int r = r8 + 8 * i;
        Ts[r][c] = src[(size_t)(k0 + r) * H3 + j0 + c];
    }
    __syncthreads();
    #pragma unroll
    for (int i = 0; i < 4; i++) {
        int r = r8 + 8 * i;
        dst[(size_t)(j0 + r) * K + k0 + c] = __float2bfloat16(Ts[c][r]);
    }
}

// -------- encoder x pre-gather: bf16 [s][b][256] (internal dst) --------
__global__ void k_xseq(const int* __restrict__ inp, const float* __restrict__ emb) {
    int s = blockIdx.x, b = blockIdx.y, t = threadIdx.x;
    int row = inp[b * SS + s];
    g_xseq[((size_t)s * BB + b) * EE + t] = __float2bfloat16(emb[(size_t)row * EE + t]);
}

// -------------------- persistent tensor-core GRU (32 CTAs) --------------------
// Same structure as round 12 (proven correct); B fragments now DEEP-PREFETCHED:
// all 16 ks-loads of a c-chunk are issued at chunk start (MLP~32), overlapped with
// the As staging loop, then the ks-loop runs purely from registers + smem.
__global__ void __launch_bounds__(256) k_gru2(
        const float* __restrict__ embd,      // harness pointer (decoder) or nullptr
        const float* __restrict__ bias,      // harness pointer
        int wsel, int xenc, int src, int nsteps, int sbase, unsigned bar_base)
{
    __shared__ __align__(16) __nv_bfloat16 As[64][264];
    const __nv_bfloat16* wxt = g_wxt[wsel];
    const __nv_bfloat16* wht = g_wht[wsel];
    int bx = blockIdx.x, t = threadIdx.x;
    int warp = t >> 5, lane = t & 31;
    int g = lane >> 2, tig = lane & 3;
    int lr = lane & 7, sel = lane >> 3;
    int arow = lr + (sel & 1) * 8;
    int acol = (sel >> 1) * 8;
    int mt = warp & 3, nh = warp >> 2;      // 4 m-tiles x 2 n-halves
    unsigned nbar = bar_base;
    int cs = src;

    for (int s = 0; s < nsteps; s++) {
        // ================= Phase 1: zr GEMM (32 cols/CTA) =================
        int jb = bx * 32;
        float acc[2][4];
        #pragma unroll
        for (int n = 0; n < 2; n++) { acc[n][0]=0.f; acc[n][1]=0.f; acc[n][2]=0.f; acc[n][3]=0.f; }

        for (int c = 0; c < 3; c++) {
            __syncthreads();                 // protect previous As consumers

            // ---- deep-prefetch ALL B fragments for this chunk (64 regs) ----
            const __nv_bfloat16* WT = (c == 0) ? wxt : wht;
            int Kd  = (c == 0) ? EE : HH;
            int kro = (c == 0) ? 0 : (c - 1) * 256;
            uint32_t bfr[2][16][2];
            #pragma unroll
            for (int nt = 0; nt < 2; nt++) {
                const __nv_bfloat16* wr =
                    WT + (size_t)(jb + nh * 16 + nt * 8 + g) * Kd + kro + 2 * tig;
                #pragma unroll
                for (int ks = 0; ks < 16; ks++) {
                    bfr[nt][ks][0] = *(const uint32_t*)(wr + ks * 16);
                    bfr[nt][ks][1] = *(const uint32_t*)(wr + ks * 16 + 8);
                }
            }

            // ---- stage As (latency overlapped with B prefetch) ----
            if (c == 0) {
                if (xenc) {
                    const uint4* sp = (const uint4*)(g_xseq + (size_t)(sbase + s) * BB * EE);
                    for (int l = t; l < 2048; l += 256) {
                        int row = l >> 5, ch = l & 31;
                        *(uint4*)&As[row][ch * 8] = sp[row * 32 + ch];
                    }
                } else {
                    for (int l = t; l < 4096; l += 256) {
                        int row = l >> 6, kk = (l & 63) * 4;
                        float4 v = *(const float4*)(embd + (size_t)g_tok[row] * EE + kk);
                        __nv_bfloat162* dp = (__nv_bfloat162*)&As[row][kk];
                        dp[0] = __floats2bfloat162_rn(v.x, v.y);
                        dp[1] = __floats2bfloat162_rn(v.z, v.w);
                    }
                }
            } else {
                const uint4* hp = (const uint4*)(g_hb[cs]);
                for (int l = t; l < 2048; l += 256) {
                    int row = l >> 5, ch = l & 31;
                    *(uint4*)&As[row][ch * 8] = __ldcg(&hp[row * 64 + (c - 1) * 32 + ch]);
                }
            }
            __syncthreads();

            // ---- consume: pure smem + tensor ----
            #pragma unroll
            for (int ks = 0; ks < 16; ks++) {
                uint32_t afr[4];
                ldsm4(afr, &As[mt * 16 + arow][ks * 16 + acol]);
                mma16816(acc[0], afr, bfr[0][ks]);
                mma16816(acc[1], afr, bfr[1][ks]);
            }
        }

        // Phase 1 epilogue
        {
            bool isZ = (jb < 512);
            #pragma unroll
            for (int nt = 0; nt < 2; nt++) {
                int col = jb + nh * 16 + nt * 8 + 2 * tig;
                float b0 = bias[col], b1 = bias[col + 1];
                #pragma unroll
                for (int half = 0; half < 2; half++) {
                    int b = mt * 16 + g + half * 8;
                    float v0 = acc[nt][half * 2 + 0];
                    float v1 = acc[nt][half * 2 + 1];
                    if (isZ) {
                        *(float2*)&g_z[b * HH + col] = make_float2(sigf(v0 + b0), sigf(v1 + b1));
                    } else {
                        int cr = col - 512;
                        float2 hv = __ldcg((const float2*)&g_h[cs][b * HH + cr]);
                        __nv_bfloat162 o;
                        o.x = __float2bfloat16(sigf(v0 + b0) * hv.x);
                        o.y = __float2bfloat16(sigf(v1 + b1) * hv.y);
                        *(__nv_bfloat162*)&g_rh[b * HH + cr] = o;
                    }
                }
            }
        }
        nbar++; gbar(nbar * GCTAS);

        // ================= Phase 2: candidate GEMM (16 cols/CTA, K=768) =================
        int cj0 = bx * 16;
        float acc2[4];
        acc2[0] = 0.f; acc2[1] = 0.f; acc2[2] = 0.f; acc2[3] = 0.f;

        for (int c = 0; c < 3; c++) {
            __syncthreads();

            // ---- deep-prefetch ALL B fragments for this chunk (32 regs) ----
            const __nv_bfloat16* WT = (c == 0) ? wxt : wht;
            int Kd  = (c == 0) ? EE : HH;
            int kro = (c == 0) ? 0 : (c - 1) * 256;
            const __nv_bfloat16* wrow =
                WT + (size_t)(1024 + cj0 + nh * 8 + g) * Kd + kro + 2 * tig;
            uint32_t bfr2[16][2];
            #pragma unroll
            for (int ks = 0; ks < 16; ks++) {
                bfr2[ks][0] = *(const uint32_t*)(wrow + ks * 16);
                bfr2[ks][1] = *(const uint32_t*)(wrow + ks * 16 + 8);
            }

            // ---- stage As ----
            if (c == 0) {
                if (xenc) {
                    const uint4* sp = (const uint4*)(g_xseq + (size_t)(sbase + s) * BB * EE);
                    for (int l = t; l < 2048; l += 256) {
                        int row = l >> 5, ch = l & 31;
                        *(uint4*)&As[row][ch * 8] = sp[row * 32 + ch];
                    }
                } else {
                    for (int l = t; l < 4096; l += 256) {
                        int row = l >> 6, kk = (l & 63) * 4;
                        float4 v = *(const float4*)(embd + (size_t)g_tok[row] * EE + kk);
                        __nv_bfloat162* dp = (__nv_bfloat162*)&As[row][kk];
                        dp[0] = __floats2bfloat162_rn(v.x, v.y);
                        dp[1] = __floats2bfloat162_rn(v.z, v.w);
                    }
                }
            } else {
                const uint4* rp = (const uint4*)g_rh;
                for (int l = t; l < 2048; l += 256) {
                    int row = l >> 5, ch = l & 31;
                    *(uint4*)&As[row][ch * 8] = __ldcg(&rp[row * 64 + (c - 1) * 32 + ch]);
                }
            }
            __syncthreads();

            // ---- consume ----
            #pragma unroll
            for (int ks = 0; ks < 16; ks++) {
                uint32_t afr[4];
                ldsm4(afr, &As[mt * 16 + arow][ks * 16 + acol]);
                mma16816(acc2, afr, bfr2[ks]);
            }
        }

        // Phase 2 epilogue: tanh + blend -> h'
        {
            int nd = cs ^ 1;
            int cj = cj0 + nh * 8 + 2 * tig;
            float b0 = bias[1024 + cj], b1 = bias[1024 + cj + 1];
            #pragma unroll
            for (int half = 0; half < 2; half++) {
                int b = mt * 16 + g + half * 8;
                float hh0 = tanhf(acc2[half * 2 + 0] + b0);
                float hh1 = tanhf(acc2[half * 2 + 1] + b1);
                float2 zv = __ldcg((const float2*)&g_z[b * HH + cj]);
                float2 hv = __ldcg((const float2*)&g_h[cs][b * HH + cj]);
                float hn0 = zv.x * hv.x + (1.0f - zv.x) * hh0;
                float hn1 = zv.y * hv.y + (1.0f - zv.y) * hh1;
                *(float2*)&g_h[nd][b * HH + cj] = make_float2(hn0, hn1);
                __nv_bfloat162 ob;
                ob.x = __float2bfloat16(hn0);
                ob.y = __float2bfloat16(hn1);
                *(__nv_bfloat162*)&g_hb[nd][b * HH + cj] = ob;
            }
        }
        nbar++; gbar(nbar * GCTAS);
        cs ^= 1;
    }
}

// -------------------- tensor-core fc (proven) --------------------
#define HS_STRIDE 264
__global__ void __launch_bounds__(256) k_fc(const float* __restrict__ fcb, int hsrc) {
    __shared__ __align__(16) __nv_bfloat16 Hs[64][HS_STRIDE];
    int t = threadIdx.x;
    int warp = t >> 5, lane = t & 31;
    int g = lane >> 2, tig = lane & 3;
    int vbase = blockIdx.x * 256 + warp * 32;

    float acc[4][4][4];
    #pragma unroll
    for (int m = 0; m < 4; m++)
        #pragma unroll
        for (int n = 0; n < 4; n++)
            { acc[m][n][0]=0.f; acc[m][n][1]=0.f; acc[m][n][2]=0.f; acc[m][n][3]=0.f; }

    int lr  = lane & 7;
    int sel = lane >> 3;
    int arow_off = lr + (sel & 1) * 8;
    int acol_off = (sel >> 1) * 8;

    for (int kh = 0; kh < 2; kh++) {
        int k0g = kh * 256;
        __syncthreads();
        for (int l = t; l < 2048; l += 256) {
            int row = l >> 5, ch = l & 31;
            const uint4* srcp = (const uint4*)(g_hb[hsrc] + row * HH + k0g);
            *(uint4*)&Hs[row][ch * 8] = srcp[ch];
        }
        __syncthreads();

        uint32_t bcur[4][2], bnxt[4][2];
        #pragma unroll
        for (int nt = 0; nt < 4; nt++) {
            const __nv_bfloat16* wr = g_wt + (size_t)(vbase + nt * 8 + g) * HH + k0g;
            bcur[nt][0] = *(const uint32_t*)(wr + 2 * tig);
            bcur[nt][1] = *(const uint32_t*)(wr + 8 + 2 * tig);
        }

        for (int ks = 0; ks < 16; ks++) {
            int kl = ks * 16;
            if (ks < 15) {
                int kn = kl + 16;
                #pragma unroll
                for (int nt = 0; nt < 4; nt++) {
                    const __nv_bfloat16* wr = g_wt + (size_t)(vbase + nt * 8 + g) * HH + k0g + kn;
                    bnxt[nt][0] = *(const uint32_t*)(wr + 2 * tig);
                    bnxt[nt][1] = *(const uint32_t*)(wr + 8 + 2 * tig);
                }
            }
            uint32_t afr[4][4];
            #pragma unroll
            for (int mt = 0; mt < 4; mt++)
                ldsm4(afr[mt], &Hs[mt * 16 + arow_off][kl + acol_off]);
            #pragma unroll
            for (int mt = 0; mt < 4; mt++)
                #pragma unroll
                for (int nt = 0; nt < 4; nt++)
                    mma16816(acc[mt][nt], afr[mt], bcur[nt]);
            if (ks < 15) {
                #pragma unroll
                for (int nt = 0; nt < 4; nt++) { bcur[nt][0] = bnxt[nt][0]; bcur[nt][1] = bnxt[nt][1]; }
            }
        }
    }

    #pragma unroll
    for (int nt = 0; nt < 4; nt++) {
        int col = vbase + nt * 8 + 2 * tig;
        float2 bv = *(const float2*)(fcb + col);
        #pragma unroll
        for (int mt = 0; mt < 4; mt++) {
            int r0 = mt * 16 + g;
            float2 o0 = make_float2(acc[mt][nt][0] + bv.x, acc[mt][nt][1] + bv.y);
            float2 o1 = make_float2(acc[mt][nt][2] + bv.x, acc[mt][nt][3] + bv.y);
            *(float2*)&g_logits[(size_t)r0 * VV + col]       = o0;
            *(float2*)&g_logits[(size_t)(r0 + 8) * VV + col] = o1;
        }
    }
}

// -------------------- per-batch loss + argmax + fused masked-mean accumulate ------------
__global__ void k_loss(const int* __restrict__ targ, int tcol, float* __restrict__ out) {
    __shared__ float sred[256];
    __shared__ float mred[256];
    __shared__ int   ired[256];
    int b = blockIdx.x, t = threadIdx.x;
    const float* lg = g_logits + (size_t)b * VV;

    float m = -3.4e38f; int mi = 0; float s1 = 0.f;
    for (int v = t; v < VV; v += 256) {
        float l = lg[v];
        s1 += expf(l);
        if (l > m) { m = l; mi = v; }
    }
    mred[t] = m; ired[t] = mi; sred[t] = s1;
    __syncthreads();
    for (int off = 128; off; off >>= 1) {
        if (t < off) {
            float mo = mred[t + off]; int io = ired[t + off];
            if (mo > mred[t] || (mo == mred[t] && io < ired[t])) { mred[t] = mo; ired[t] = io; }
            sred[t] += sred[t + off];
        }
        __syncthreads();
    }
    float inv_s1 = 1.0f / sred[0];
    int argmax = ired[0];
    __syncthreads();

    float s2 = 0.f;
    for (int v = t; v < VV; v += 256)
        s2 += expf(expf(lg[v]) * inv_s1);
    sred[t] = s2;
    __syncthreads();
    for (int off = 128; off; off >>= 1) {
        if (t < off) sred[t] += sred[t + off];
        __syncthreads();
    }
    if (t == 0) {
        int tgt = targ[b * TT + tcol];
        float pt = expf(lg[tgt]) * inv_s1;
        float ce = logf(sred[0]) - pt;
        float mask = (tgt != 0) ? 1.0f : 0.0f;
        atomicAdd(out, ce * mask * (1.0f / 64.0f));
        g_tok[b] = argmax;
    }
}

// -------------------- launch (NO device-global addresses cross this boundary) -----------
extern "C" void kernel_launch(void* const* d_in, const int* in_sizes, int n_in,
                              void* d_out, int out_size)
{
    const int*   inp     = (const int*)  d_in[0];
    const int*   targ    = (const int*)  d_in[1];
    const float* emb_enc = (const float*)d_in[2];
    const float* enc_Wx  = (const float*)d_in[3];
    const float* enc_Wh  = (const float*)d_in[4];
    const float* enc_b   = (const float*)d_in[5];
    const float* emb_dec = (const float*)d_in[6];
    const float* dec_Wx  = (const float*)d_in[7];
    const float* dec_Wh  = (const float*)d_in[8];
    const float* dec_b   = (const float*)d_in[9];
    const float* fc_W    = (const float*)d_in[10];
    const float* fc_b    = (const float*)d_in[11];
    float* out = (float*)d_out;

    k_init<<<BB, HH>>>(out);
    k_prept<<<dim3(1000, 16), 256>>>(fc_W);
    k_prepw<<<dim3(48, 8),  256>>>(enc_Wx, 0, EE);
    k_prepw<<<dim3(48, 16), 256>>>(enc_Wh, 1, HH);
    k_prepw<<<dim3(48, 8),  256>>>(dec_Wx, 2, EE);
    k_prepw<<<dim3(48, 16), 256>>>(dec_Wh, 3, HH);
    k_xseq<<<dim3(SS, BB), EE>>>(inp, emb_enc);

    unsigned barb = 0;
    // encoder: 64 GRU steps, ONE launch
    k_gru2<<<GCTAS, 256>>>(nullptr, enc_b, 0, 1, 0, SS, 0, barb);
    barb += 2 * SS;

    int src = 0;   // SS even -> final encoder state in buffer 0
    for (int tt = 1; tt < TT; tt++) {
        k_gru2<<<GCTAS, 256>>>(emb_dec, dec_b, 1, 0, src, 1, 0, barb);
        barb += 2;
        src ^= 1;
        k_fc<<<125, 256>>>(fc_b, src);
        k_loss<<<BB, 256>>>(targ, tt, out);
    }
}

// round 14
// speedup vs baseline: 1.4743x; 1.0305x over previous
#include <cuda_runtime.h>
#include <cuda_bf16.h>
#include <math.h>
#include <stdint.h>

// Problem constants
#define BB   64      // batch
#define SS   64      // encoder seq len
#define TT   32      // decoder target len
#define VV   32000   // vocab
#define EE   256     // embedding
#define HH   512     // hidden
#define H3   1536    // 3*H
#define GCTAS 32     // GRU grid (single wave, cheap 32-way barrier)

// ---------- device scratch (static; NEVER passed as kernel args from host) ----------
__device__ __align__(16) float          g_h[2][BB * HH];     // hidden fp32, double buffered
__device__ __align__(16) __nv_bfloat16  g_hb[2][BB * HH];    // hidden bf16, double buffered
__device__ __align__(16) float          g_z[BB * HH];        // sigmoid(z-gate)
__device__ __align__(16) __nv_bfloat16  g_rh[BB * HH];       // bf16(r * h)
__device__ __align__(16) __nv_bfloat16  g_xseq[SS * BB * EE];  // encoder x bf16 [s][b][k]
__device__ __align__(16) __nv_bfloat16  g_wxt[2][H3 * EE];   // Wx^T [col][k] bf16 (0=enc,1=dec)
__device__ __align__(16) __nv_bfloat16  g_wht[2][H3 * HH];   // Wh^T [col][k] bf16
__device__ __align__(16) __nv_bfloat16  g_wt[(size_t)VV * HH]; // fc_W^T [v][k] bf16
__device__ __align__(16) float          g_logits[(size_t)BB * VV];
__device__ int                          g_tok[BB];
__device__ unsigned                     g_bar;

__device__ __forceinline__ float sigf(float x) { return 1.0f / (1.0f + expf(-x)); }

// 32-CTA counting barrier: hot spin on one L2 line.
__device__ __forceinline__ void gbar(unsigned target) {
    __syncthreads();
    if (threadIdx.x == 0) {
        __threadfence();                   // release
        atomicAdd(&g_bar, 1u);
        volatile unsigned* vp = &g_bar;
        while (*vp < target) {}
    }
    __syncthreads();
    __threadfence();                       // acquire
}

// ---------- mma helpers (fragment layout proven rounds 4/9/11/12/13) ----------
__device__ __forceinline__ void mma16816(float* d, const uint32_t* a, const uint32_t* b) {
    asm volatile(
        "mma.sync.aligned.m16n8k16.row.col.f32.bf16.bf16.f32 "
        "{%0,%1,%2,%3},{%4,%5,%6,%7},{%8,%9},{%0,%1,%2,%3};\n"
        : "+f"(d[0]), "+f"(d[1]), "+f"(d[2]), "+f"(d[3])
        : "r"(a[0]), "r"(a[1]), "r"(a[2]), "r"(a[3]), "r"(b[0]), "r"(b[1]));
}
__device__ __forceinline__ void ldsm4(uint32_t* a, const void* p) {
    uint32_t saddr = (uint32_t)__cvta_generic_to_shared(p);
    asm volatile("ldmatrix.sync.aligned.m8n8.x4.shared.b16 {%0,%1,%2,%3},[%4];\n"
        : "=r"(a[0]), "=r"(a[1]), "=r"(a[2]), "=r"(a[3]) : "r"(saddr));
}

// -------------------- init --------------------
__global__ void k_init(float* out) {
    int b = blockIdx.x, t = threadIdx.x;
    g_h[0][b * HH + t] = 0.0f;
    g_hb[0][b * HH + t] = __float2bfloat16(0.0f);
    if (t == 0) g_tok[b] = 1;              // BEGIN token
    if (b == 0 && t == 0) { out[0] = 0.0f; g_bar = 0u; }
}

// -------- fc_W [k][v] fp32 -> g_wt [v][k] bf16 (internal dst; proven) --------
__global__ void k_prept(const float* __restrict__ fcW) {
    __shared__ float Ts[32][33];
    int v0 = blockIdx.x * 32, k0 = blockIdx.y * 32;
    int c = threadIdx.x & 31, r8 = threadIdx.x >> 5;
    #pragma unroll
    for (int i = 0; i < 4; i++) {
        int r = r8 + 8 * i;
        Ts[r][c] = fcW[(size_t)(k0 + r) * VV + v0 + c];
    }
    __syncthreads();
    #pragma unroll
    for (int i = 0; i < 4; i++) {
        int r = r8 + 8 * i;
        g_wt[(size_t)(v0 + r) * HH + k0 + c] = __float2bfloat16(Ts[c][r]);
    }
}

// -------- ALL GRU weight transposes in ONE launch: fp32 [K][1536] -> bf16 [1536][K] -----
// grid = (48, 48): y<8 encWx | y<24 encWh | y<32 decWx | else decWh
__global__ void k_prepw4(const float* __restrict__ wxe, const float* __restrict__ whe,
                         const float* __restrict__ wxd, const float* __restrict__ whd) {
    __shared__ float Ts[32][33];
    int y = blockIdx.y;
    const float* src; __nv_bfloat16* dst; int K, k0;
    if (y < 8)       { src = wxe; dst = g_wxt[0]; K = EE; k0 = y * 32; }
    else if (y < 24) { src = whe; dst = g_wht[0]; K = HH; k0 = (y - 8) * 32; }
    else if (y < 32) { src = wxd; dst = g_wxt[1]; K = EE; k0 = (y - 24) * 32; }
    else             { src = whd; dst = g_wht[1]; K = HH; k0 = (y - 32) * 32; }
    int j0 = blockIdx.x * 32;
    int c = threadIdx.x & 31, r8 = threadIdx.x >> 5;
    #pragma unroll
    for (int i = 0; i < 4; i++) {
        int r = r8 + 8 * i;
        Ts[r][c] = src[(size_t)(k0 + r) * H3 + j0 + c];
    }
    __syncthreads();
    #pragma unroll
    for (int i = 0; i < 4; i++) {
        int r = r8 + 8 * i;
        dst[(size_t)(j0 + r) * K + k0 + c] = __float2bfloat16(Ts[c][r]);
    }
}

// -------- encoder x pre-gather: bf16 [s][b][256] (internal dst) --------
__global__ void k_xseq(const int* __restrict__ inp, const float* __restrict__ emb) {
    int s = blockIdx.x, b = blockIdx.y, t = threadIdx.x;
    int row = inp[b * SS + s];
    g_xseq[((size_t)s * BB + b) * EE + t] = __float2bfloat16(emb[(size_t)row * EE + t]);
}

// -------------------- persistent tensor-core GRU (32 CTAs) --------------------
// Phase 1: zr GEMM (cols [0,1024), 32 cols/CTA) over K=768; at its c=0 (x) chunk it ALSO
//   accumulates the candidate x-part (cols 1024+cj0, 16/CTA) into acc2 (x staged once!).
// Phase 2: candidate rh chunks only (2 chunks, K=512) + tanh/blend epilogue.
// 2 barriers/step. B fragments deep-prefetched per chunk. FP order = x, rh-lo, rh-hi
// (identical to round 13 -> same numerics).
__global__ void __launch_bounds__(256) k_gru2(
        const float* __restrict__ embd,      // harness pointer (decoder) or nullptr
        const float* __restrict__ bias,      // harness pointer
        int wsel, int xenc, int src, int nsteps, int sbase, unsigned bar_base)
{
    __shared__ __align__(16) __nv_bfloat16 As[64][264];
    const __nv_bfloat16* wxt = g_wxt[wsel];
    const __nv_bfloat16* wht = g_wht[wsel];
    int bx = blockIdx.x, t = threadIdx.x;
    int warp = t >> 5, lane = t & 31;
    int g = lane >> 2, tig = lane & 3;
    int lr = lane & 7, sel = lane >> 3;
    int arow = lr + (sel & 1) * 8;
    int acol = (sel >> 1) * 8;
    int mt = warp & 3, nh = warp >> 2;      // 4 m-tiles x 2 n-halves
    unsigned nbar = bar_base;
    int cs = src;
    int jb  = bx * 32;                      // phase-1 col tile
    int cj0 = bx * 16;                      // phase-2 col tile

    for (int s = 0; s < nsteps; s++) {
        // ================= Phase 1: zr GEMM + candidate x-part =================
        float acc[2][4];
        #pragma unroll
        for (int n = 0; n < 2; n++) { acc[n][0]=0.f; acc[n][1]=0.f; acc[n][2]=0.f; acc[n][3]=0.f; }
        float acc2[4];
        acc2[0] = 0.f; acc2[1] = 0.f; acc2[2] = 0.f; acc2[3] = 0.f;

        for (int c = 0; c < 3; c++) {
            __syncthreads();                 // protect previous As consumers

            // ---- deep-prefetch B fragments for this chunk ----
            const __nv_bfloat16* WT = (c == 0) ? wxt : wht;
            int Kd  = (c == 0) ? EE : HH;
            int kro = (c == 0) ? 0 : (c - 1) * 256;
            uint32_t bfr[2][16][2];
            #pragma unroll
            for (int nt = 0; nt < 2; nt++) {
                const __nv_bfloat16* wr =
                    WT + (size_t)(jb + nh * 16 + nt * 8 + g) * Kd + kro + 2 * tig;
                #pragma unroll
                for (int ks = 0; ks < 16; ks++) {
                    bfr[nt][ks][0] = *(const uint32_t*)(wr + ks * 16);
                    bfr[nt][ks][1] = *(const uint32_t*)(wr + ks * 16 + 8);
                }
            }
            // candidate x-part fragments (c==0 only)
            uint32_t bfr2x[16][2];
            if (c == 0) {
                const __nv_bfloat16* wr =
                    wxt + (size_t)(1024 + cj0 + nh * 8 + g) * EE + 2 * tig;
                #pragma unroll
                for (int ks = 0; ks < 16; ks++) {
                    bfr2x[ks][0] = *(const uint32_t*)(wr + ks * 16);
                    bfr2x[ks][1] = *(const uint32_t*)(wr + ks * 16 + 8);
                }
            }

            // ---- stage As (latency overlapped with B prefetch) ----
            if (c == 0) {
                if (xenc) {
                    const uint4* sp = (const uint4*)(g_xseq + (size_t)(sbase + s) * BB * EE);
                    for (int l = t; l < 2048; l += 256) {
                        int row = l >> 5, ch = l & 31;
                        *(uint4*)&As[row][ch * 8] = sp[row * 32 + ch];
                    }
                } else {
                    for (int l = t; l < 4096; l += 256) {
                        int row = l >> 6, kk = (l & 63) * 4;
                        float4 v = *(const float4*)(embd + (size_t)g_tok[row] * EE + kk);
                        __nv_bfloat162* dp = (__nv_bfloat162*)&As[row][kk];
                        dp[0] = __floats2bfloat162_rn(v.x, v.y);
                        dp[1] = __floats2bfloat162_rn(v.z, v.w);
                    }
                }
            } else {
                const uint4* hp = (const uint4*)(g_hb[cs]);
                for (int l = t; l < 2048; l += 256) {
                    int row = l >> 5, ch = l & 31;
                    *(uint4*)&As[row][ch * 8] = __ldcg(&hp[row * 64 + (c - 1) * 32 + ch]);
                }
            }
            __syncthreads();

            // ---- consume: pure smem + tensor ----
            if (c == 0) {
                #pragma unroll
                for (int ks = 0; ks < 16; ks++) {
                    uint32_t afr[4];
                    ldsm4(afr, &As[mt * 16 + arow][ks * 16 + acol]);
                    mma16816(acc[0], afr, bfr[0][ks]);
                    mma16816(acc[1], afr, bfr[1][ks]);
                    mma16816(acc2,   afr, bfr2x[ks]);
                }
            } else {
                #pragma unroll
                for (int ks = 0; ks < 16; ks++) {
                    uint32_t afr[4];
                    ldsm4(afr, &As[mt * 16 + arow][ks * 16 + acol]);
                    mma16816(acc[0], afr, bfr[0][ks]);
                    mma16816(acc[1], afr, bfr[1][ks]);
                }
            }
        }

        // Phase 1 epilogue (z / rh)
        {
            bool isZ = (jb < 512);
            #pragma unroll
            for (int nt = 0; nt < 2; nt++) {
                int col = jb + nh * 16 + nt * 8 + 2 * tig;
                float b0 = bias[col], b1 = bias[col + 1];
                #pragma unroll
                for (int half = 0; half < 2; half++) {
                    int b = mt * 16 + g + half * 8;
                    float v0 = acc[nt][half * 2 + 0];
                    float v1 = acc[nt][half * 2 + 1];
                    if (isZ) {
                        *(float2*)&g_z[b * HH + col] = make_float2(sigf(v0 + b0), sigf(v1 + b1));
                    } else {
                        int cr = col - 512;
                        float2 hv = __ldcg((const float2*)&g_h[cs][b * HH + cr]);
                        __nv_bfloat162 o;
                        o.x = __float2bfloat16(sigf(v0 + b0) * hv.x);
                        o.y = __float2bfloat16(sigf(v1 + b1) * hv.y);
                        *(__nv_bfloat162*)&g_rh[b * HH + cr] = o;
                    }
                }
            }
        }
        nbar++; gbar(nbar * GCTAS);

        // ================= Phase 2: candidate rh chunks (2 chunks, K=512) =================
        for (int c = 1; c < 3; c++) {
            __syncthreads();

            const __nv_bfloat16* wrow =
                wht + (size_t)(1024 + cj0 + nh * 8 + g) * HH + (c - 1) * 256 + 2 * tig;
            uint32_t bfr2[16][2];
            #pragma unroll
            for (int ks = 0; ks < 16; ks++) {
                bfr2[ks][0] = *(const uint32_t*)(wrow + ks * 16);
                bfr2[ks][1] = *(const uint32_t*)(wrow + ks * 16 + 8);
            }

            const uint4* rp = (const uint4*)g_rh;
            for (int l = t; l < 2048; l += 256) {
                int row = l >> 5, ch = l & 31;
                *(uint4*)&As[row][ch * 8] = __ldcg(&rp[row * 64 + (c - 1) * 32 + ch]);
            }
            __syncthreads();

            #pragma unroll
            for (int ks = 0; ks < 16; ks++) {
                uint32_t afr[4];
                ldsm4(afr, &As[mt * 16 + arow][ks * 16 + acol]);
                mma16816(acc2, afr, bfr2[ks]);
            }
        }

        // Phase 2 epilogue: tanh + blend -> h'
        {
            int nd = cs ^ 1;
            int cj = cj0 + nh * 8 + 2 * tig;
            float b0 = bias[1024 + cj], b1 = bias[1024 + cj + 1];
            #pragma unroll
            for (int half = 0; half < 2; half++) {
                int b = mt * 16 + g + half * 8;
                float hh0 = tanhf(acc2[half * 2 + 0] + b0);
                float hh1 = tanhf(acc2[half * 2 + 1] + b1);
                float2 zv = __ldcg((const float2*)&g_z[b * HH + cj]);
                float2 hv = __ldcg((const float2*)&g_h[cs][b * HH + cj]);
                float hn0 = zv.x * hv.x + (1.0f - zv.x) * hh0;
                float hn1 = zv.y * hv.y + (1.0f - zv.y) * hh1;
                *(float2*)&g_h[nd][b * HH + cj] = make_float2(hn0, hn1);
                __nv_bfloat162 ob;
                ob.x = __float2bfloat16(hn0);
                ob.y = __float2bfloat16(hn1);
                *(__nv_bfloat162*)&g_hb[nd][b * HH + cj] = ob;
            }
        }
        nbar++; gbar(nbar * GCTAS);
        cs ^= 1;
    }
}

// -------------------- tensor-core fc (proven) --------------------
#define HS_STRIDE 264
__global__ void __launch_bounds__(256) k_fc(const float* __restrict__ fcb, int hsrc) {
    __shared__ __align__(16) __nv_bfloat16 Hs[64][HS_STRIDE];
    int t = threadIdx.x;
    int warp = t >> 5, lane = t & 31;
    int g = lane >> 2, tig = lane & 3;
    int vbase = blockIdx.x * 256 + warp * 32;

    float acc[4][4][4];
    #pragma unroll
    for (int m = 0; m < 4; m++)
        #pragma unroll
        for (int n = 0; n < 4; n++)
            { acc[m][n][0]=0.f; acc[m][n][1]=0.f; acc[m][n][2]=0.f; acc[m][n][3]=0.f; }

    int lr  = lane & 7;
    int sel = lane >> 3;
    int arow_off = lr + (sel & 1) * 8;
    int acol_off = (sel >> 1) * 8;

    for (int kh = 0; kh < 2; kh++) {
        int k0g = kh * 256;
        __syncthreads();
        for (int l = t; l < 2048; l += 256) {
            int row = l >> 5, ch = l & 31;
            const uint4* srcp = (const uint4*)(g_hb[hsrc] + row * HH + k0g);
            *(uint4*)&Hs[row][ch * 8] = srcp[ch];
        }
        __syncthreads();

        uint32_t bcur[4][2], bnxt[4][2];
        #pragma unroll
        for (int nt = 0; nt < 4; nt++) {
            const __nv_bfloat16* wr = g_wt + (size_t)(vbase + nt * 8 + g) * HH + k0g;
            bcur[nt][0] = *(const uint32_t*)(wr + 2 * tig);
            bcur[nt][1] = *(const uint32_t*)(wr + 8 + 2 * tig);
        }

        for (int ks = 0; ks < 16; ks++) {
            int kl = ks * 16;
            if (ks < 15) {
                int kn = kl + 16;
                #pragma unroll
                for (int nt = 0; nt < 4; nt++) {
                    const __nv_bfloat16* wr = g_wt + (size_t)(vbase + nt * 8 + g) * HH + k0g + kn;
                    bnxt[nt][0] = *(const uint32_t*)(wr + 2 * tig);
                    bnxt[nt][1] = *(const uint32_t*)(wr + 8 + 2 * tig);
                }
            }
            uint32_t afr[4][4];
            #pragma unroll
            for (int mt = 0; mt < 4; mt++)
                ldsm4(afr[mt], &Hs[mt * 16 + arow_off][kl + acol_off]);
            #pragma unroll
            for (int mt = 0; mt < 4; mt++)
                #pragma unroll
                for (int nt = 0; nt < 4; nt++)
                    mma16816(acc[mt][nt], afr[mt], bcur[nt]);
            if (ks < 15) {
                #pragma unroll
                for (int nt = 0; nt < 4; nt++) { bcur[nt][0] = bnxt[nt][0]; bcur[nt][1] = bnxt[nt][1]; }
            }
        }
    }

    #pragma unroll
    for (int nt = 0; nt < 4; nt++) {
        int col = vbase + nt * 8 + 2 * tig;
        float2 bv = *(const float2*)(fcb + col);
        #pragma unroll
        for (int mt = 0; mt < 4; mt++) {
            int r0 = mt * 16 + g;
            float2 o0 = make_float2(acc[mt][nt][0] + bv.x, acc[mt][nt][1] + bv.y);
            float2 o1 = make_float2(acc[mt][nt][2] + bv.x, acc[mt][nt][3] + bv.y);
            *(float2*)&g_logits[(size_t)r0 * VV + col]       = o0;
            *(float2*)&g_logits[(size_t)(r0 + 8) * VV + col] = o1;
        }
    }
}

// -------------------- per-batch loss + argmax + fused masked-mean accumulate ------------
__global__ void k_loss(const int* __restrict__ targ, int tcol, float* __restrict__ out) {
    __shared__ float sred[256];
    __shared__ float mred[256];
    __shared__ int   ired[256];
    int b = blockIdx.x, t = threadIdx.x;
    const float* lg = g_logits + (size_t)b * VV;

    float m = -3.4e38f; int mi = 0; float s1 = 0.f;
    for (int v = t; v < VV; v += 256) {
        float l = lg[v];
        s1 += expf(l);
        if (l > m) { m = l; mi = v; }
    }
    mred[t] = m; ired[t] = mi; sred[t] = s1;
    __syncthreads();
    for (int off = 128; off; off >>= 1) {
        if (t < off) {
            float mo = mred[t + off]; int io = ired[t + off];
            if (mo > mred[t] || (mo == mred[t] && io < ired[t])) { mred[t] = mo; ired[t] = io; }
            sred[t] += sred[t + off];
        }
        __syncthreads();
    }
    float inv_s1 = 1.0f / sred[0];
    int argmax = ired[0];
    __syncthreads();

    float s2 = 0.f;
    for (int v = t; v < VV; v += 256)
        s2 += expf(expf(lg[v]) * inv_s1);
    sred[t] = s2;
    __syncthreads();
    for (int off = 128; off; off >>= 1) {
        if (t < off) sred[t] += sred[t + off];
        __syncthreads();
    }
    if (t == 0) {
        int tgt = targ[b * TT + tcol];
        float pt = expf(lg[tgt]) * inv_s1;
        float ce = logf(sred[0]) - pt;
        float mask = (tgt != 0) ? 1.0f : 0.0f;
        atomicAdd(out, ce * mask * (1.0f / 64.0f));
        g_tok[b] = argmax;
    }
}

// -------------------- launch (NO device-global addresses cross this boundary) -----------
extern "C" void kernel_launch(void* const* d_in, const int* in_sizes, int n_in,
                              void* d_out, int out_size)
{
    const int*   inp     = (const int*)  d_in[0];
    const int*   targ    = (const int*)  d_in[1];
    const float* emb_enc = (const float*)d_in[2];
    const float* enc_Wx  = (const float*)d_in[3];
    const float* enc_Wh  = (const float*)d_in[4];
    const float* enc_b   = (const float*)d_in[5];
    const float* emb_dec = (const float*)d_in[6];
    const float* dec_Wx  = (const float*)d_in[7];
    const float* dec_Wh  = (const float*)d_in[8];
    const float* dec_b   = (const float*)d_in[9];
    const float* fc_W    = (const float*)d_in[10];
    const float* fc_b    = (const float*)d_in[11];
    float* out = (float*)d_out;

    k_init<<<BB, HH>>>(out);                                    // launch 1
    k_prept<<<dim3(1000, 16), 256>>>(fc_W);                     // launch 2
    k_prepw4<<<dim3(48, 48), 256>>>(enc_Wx, enc_Wh, dec_Wx, dec_Wh); // launch 3
    k_xseq<<<dim3(SS, BB), EE>>>(inp, emb_enc);                 // launch 4

    unsigned barb = 0;
    // encoder: 64 GRU steps, ONE launch                         // launch 5
    k_gru2<<<GCTAS, 256>>>(nullptr, enc_b, 0, 1, 0, SS, 0, barb);
    barb += 2 * SS;

    int src = 0;   // SS even -> final encoder state in buffer 0
    for (int tt = 1; tt < TT; tt++) {
        // launch 6 on first iteration -> ncu (-s 5 -c 1) captures a decoder GRU step
        k_gru2<<<GCTAS, 256>>>(emb_dec, dec_b, 1, 0, src, 1, 0, barb);
        barb += 2;
        src ^= 1;
        k_fc<<<125, 256>>>(fc_b, src);
        k_loss<<<BB, 256>>>(targ, tt, out);
    }
}

// round 17
// speedup vs baseline: 1.5098x; 1.0241x over previous
#include <cuda_runtime.h>
#include <cuda_bf16.h>
#include <math.h>
#include <stdint.h>

// Problem constants
#define BB   64      // batch
#define SS   64      // encoder seq len
#define TT   32      // decoder target len
#define VV   32000   // vocab
#define EE   256     // embedding
#define HH   512     // hidden
#define H3   1536    // 3*H
#define GCTAS 32     // GRU grid (single wave, cheap 32-way barrier)

#define AS_STRIDE 264
#define AS_TILE   (64 * AS_STRIDE)                 // one K=256 chunk tile
#define SMEM_GRU  (3 * AS_TILE * (int)sizeof(__nv_bfloat16))   // 101,376 B

// ---------- device scratch (static; NEVER passed as kernel args from host) ----------
__device__ __align__(16) float          g_h[2][BB * HH];
__device__ __align__(16) __nv_bfloat16  g_hb[2][BB * HH];
__device__ __align__(16) float          g_z[BB * HH];
__device__ __align__(16) __nv_bfloat16  g_rh[BB * HH];
__device__ __align__(16) __nv_bfloat16  g_xseq[SS * BB * EE];
__device__ __align__(16) __nv_bfloat16  g_wxt[2][H3 * EE];
__device__ __align__(16) __nv_bfloat16  g_wht[2][H3 * HH];
__device__ __align__(16) __nv_bfloat16  g_wt[(size_t)VV * HH];
__device__ __align__(16) float          g_logits[(size_t)BB * VV];
__device__ int                          g_tok[BB];
__device__ unsigned                     g_bar;

__device__ __forceinline__ float sigf(float x) { return 1.0f / (1.0f + expf(-x)); }

// 32-CTA counting barrier: hot spin on one L2 line.
__device__ __forceinline__ void gbar(unsigned target) {
    __syncthreads();
    if (threadIdx.x == 0) {
        __threadfence();                   // release
        atomicAdd(&g_bar, 1u);
        volatile unsigned* vp = &g_bar;
        while (*vp < target) {}
    }
    __syncthreads();
    __threadfence();                       // acquire
}

// ---------- mma helpers (fragment layout proven rounds 4/9/11-14) ----------
__device__ __forceinline__ void mma16816(float* d, const uint32_t* a, const uint32_t* b) {
    asm volatile(
        "mma.sync.aligned.m16n8k16.row.col.f32.bf16.bf16.f32 "
        "{%0,%1,%2,%3},{%4,%5,%6,%7},{%8,%9},{%0,%1,%2,%3};\n"
        : "+f"(d[0]), "+f"(d[1]), "+f"(d[2]), "+f"(d[3])
        : "r"(a[0]), "r"(a[1]), "r"(a[2]), "r"(a[3]), "r"(b[0]), "r"(b[1]));
}
__device__ __forceinline__ void ldsm4(uint32_t* a, const void* p) {
    uint32_t saddr = (uint32_t)__cvta_generic_to_shared(p);
    asm volatile("ldmatrix.sync.aligned.m8n8.x4.shared.b16 {%0,%1,%2,%3},[%4];\n"
        : "=r"(a[0]), "=r"(a[1]), "=r"(a[2]), "=r"(a[3]) : "r"(saddr));
}

// -------------------- init --------------------
__global__ void k_init(float* out) {
    int b = blockIdx.x, t = threadIdx.x;
    g_h[0][b * HH + t] = 0.0f;
    g_hb[0][b * HH + t] = __float2bfloat16(0.0f);
    if (t == 0) g_tok[b] = 1;              // BEGIN token
    if (b == 0 && t == 0) { out[0] = 0.0f; g_bar = 0u; }
}

// -------- fc_W [k][v] fp32 -> g_wt [v][k] bf16 (proven) --------
__global__ void k_prept(const float* __restrict__ fcW) {
    __shared__ float Ts[32][33];
    int v0 = blockIdx.x * 32, k0 = blockIdx.y * 32;
    int c = threadIdx.x & 31, r8 = threadIdx.x >> 5;
    #pragma unroll
    for (int i = 0; i < 4; i++) {
        int r = r8 + 8 * i;
        Ts[r][c] = fcW[(size_t)(k0 + r) * VV + v0 + c];
    }
    __syncthreads();
    #pragma unroll
    for (int i = 0; i < 4; i++) {
        int r = r8 + 8 * i;
        g_wt[(size_t)(v0 + r) * HH + k0 + c] = __float2bfloat16(Ts[c][r]);
    }
}

// -------- FUSED: all 4 GRU weight transposes + encoder x pre-gather (one launch) --------
// bx < 2304: weight transpose tile (48 x 48 grid flattened)
// bx >= 2304: xseq gather, idx = bx - 2304 -> (s = idx & 63, b = idx >> 6)
__global__ void k_prep_all(const float* __restrict__ wxe, const float* __restrict__ whe,
                           const float* __restrict__ wxd, const float* __restrict__ whd,
                           const int* __restrict__ inp, const float* __restrict__ emb) {
    int bxx = blockIdx.x;
    if (bxx < 2304) {
        __shared__ float Ts[32][33];
        int jx = bxx % 48, y = bxx / 48;
        const float* src; __nv_bfloat16* dst; int K, k0;
        if (y < 8)       { src = wxe; dst = g_wxt[0]; K = EE; k0 = y * 32; }
        else if (y < 24) { src = whe; dst = g_wht[0]; K = HH; k0 = (y - 8) * 32; }
        else if (y < 32) { src = wxd; dst = g_wxt[1]; K = EE; k0 = (y - 24) * 32; }
        else             { src = whd; dst = g_wht[1]; K = HH; k0 = (y - 32) * 32; }
        int j0 = jx * 32;
        int c = threadIdx.x & 31, r8 = threadIdx.x >> 5;
        #pragma unroll
        for (int i = 0; i < 4; i++) {
            int r = r8 + 8 * i;
            Ts[r][c] = src[(size_t)(k0 + r) * H3 + j0 + c];
        }
        __syncthreads();
        #pragma unroll
        for (int i = 0; i < 4; i++) {
            int r = r8 + 8 * i;
            dst[(size_t)(j0 + r) * K + k0 + c] = __float2bfloat16(Ts[c][r]);
        }
    } else {
        int idx = bxx - 2304;
        int s = idx & 63, b = idx >> 6;
        int t = threadIdx.x;
        int row = inp[b * SS + s];
        g_xseq[((size_t)s * BB + b) * EE + t] = __float2bfloat16(emb[(size_t)row * EE + t]);
    }
}

// -------------------- persistent tensor-core GRU (32 CTAs, 101KB smem) --------------------
// Phase 1: stage x|h-lo|h-hi into 3 disjoint smem tiles (ONE sync), consume 3 chunks
//   back-to-back with ping-pong B prefetch. zr epilogue; candidate x-part fused at c=0.
// Phase 2: stage rh-lo|rh-hi into tiles 1,2 (ONE sync), consume with ping-pong B.
//   tanh/blend epilogue.   2 barriers/step. FP order x, rh-lo, rh-hi (same as r13/14).
__global__ void __launch_bounds__(256) k_gru2(
        const float* __restrict__ embd,      // harness pointer (decoder) or nullptr
        const float* __restrict__ bias,      // harness pointer
        int wsel, int xenc, int src, int nsteps, int sbase, unsigned bar_base)
{
    extern __shared__ __align__(16) __nv_bfloat16 As[];   // 3 tiles of [64][AS_STRIDE]
    const __nv_bfloat16* wxt = g_wxt[wsel];
    const __nv_bfloat16* wht = g_wht[wsel];
    int bx = blockIdx.x, t = threadIdx.x;
    int warp = t >> 5, lane = t & 31;
    int g = lane >> 2, tig = lane & 3;
    int lr = lane & 7, sel = lane >> 3;
    int arow = lr + (sel & 1) * 8;
    int acol = (sel >> 1) * 8;
    int mt = warp & 3, nh = warp >> 2;      // 4 m-tiles x 2 n-halves
    unsigned nbar = bar_base;
    int cs = src;
    int jb  = bx * 32;                      // phase-1 col tile
    int cj0 = bx * 16;                      // phase-2 col tile

    // chunk parameters: c=0 -> (wxt, EE, 0); c=1/2 -> (wht, HH, (c-1)*256)
    auto loadB1 = [&](uint32_t (*dst)[2], int c) {      // 32 regs (2 n-tiles x 16ks)
        const __nv_bfloat16* WT = (c == 0) ? wxt : wht;
        int Kd  = (c == 0) ? EE : HH;
        int kro = (c == 0) ? 0 : (c - 1) * 256;
        #pragma unroll
        for (int nt = 0; nt < 2; nt++) {
            const __nv_bfloat16* wr =
                WT + (size_t)(jb + nh * 16 + nt * 8 + g) * Kd + kro + 2 * tig;
            #pragma unroll
            for (int ks = 0; ks < 16; ks++) {
                dst[nt * 16 + ks][0] = *(const uint32_t*)(wr + ks * 16);
                dst[nt * 16 + ks][1] = *(const uint32_t*)(wr + ks * 16 + 8);
            }
        }
    };

    for (int s = 0; s < nsteps; s++) {
        // ================= Phase 1 =================
        float acc[2][4];
        #pragma unroll
        for (int n = 0; n < 2; n++) { acc[n][0]=0.f; acc[n][1]=0.f; acc[n][2]=0.f; acc[n][3]=0.f; }
        float acc2[4];
        acc2[0] = 0.f; acc2[1] = 0.f; acc2[2] = 0.f; acc2[3] = 0.f;

        uint32_t bpA[32][2], bpB[32][2];    // ping-pong chunk B fragments
        uint32_t bfr2x[16][2];              // candidate x-part fragments (c=0)

        // issue B(0) + candidate-x B, then stage ALL As tiles (overlaps latency)
        loadB1(bpA, 0);
        {
            const __nv_bfloat16* wr =
                wxt + (size_t)(1024 + cj0 + nh * 8 + g) * EE + 2 * tig;
            #pragma unroll
            for (int ks = 0; ks < 16; ks++) {
                bfr2x[ks][0] = *(const uint32_t*)(wr + ks * 16);
                bfr2x[ks][1] = *(const uint32_t*)(wr + ks * 16 + 8);
            }
        }

        // ---- stage: x -> tile0, h-lo -> tile1, h-hi -> tile2 (no intermediate syncs) ----
        if (xenc) {
            const uint4* sp = (const uint4*)(g_xseq + (size_t)(sbase + s) * BB * EE);
            for (int l = t; l < 2048; l += 256) {
                int row = l >> 5, ch = l & 31;
                *(uint4*)&As[row * AS_STRIDE + ch * 8] = sp[row * 32 + ch];
            }
        } else {
            for (int l = t; l < 4096; l += 256) {
                int row = l >> 6, kk = (l & 63) * 4;
                float4 v = *(const float4*)(embd + (size_t)g_tok[row] * EE + kk);
                __nv_bfloat162* dp = (__nv_bfloat162*)&As[row * AS_STRIDE + kk];
                dp[0] = __floats2bfloat162_rn(v.x, v.y);
                dp[1] = __floats2bfloat162_rn(v.z, v.w);
            }
        }
        {
            const uint4* hp = (const uint4*)(g_hb[cs]);
            for (int l = t; l < 4096; l += 256) {
                int half = l >> 11;                   // 0 = lo, 1 = hi
                int li = l & 2047;
                int row = li >> 5, ch = li & 31;
                *(uint4*)&As[(1 + half) * AS_TILE + row * AS_STRIDE + ch * 8] =
                    __ldcg(&hp[row * 64 + half * 32 + ch]);
            }
        }
        __syncthreads();

        // ---- consume 3 chunks, ping-pong B ----
        loadB1(bpB, 1);                                // prefetch chunk 1
        #pragma unroll
        for (int ks = 0; ks < 16; ks++) {              // consume chunk 0 (x) + cand-x
            uint32_t afr[4];
            ldsm4(afr, &As[(mt * 16 + arow) * AS_STRIDE + ks * 16 + acol]);
            mma16816(acc[0], afr, bpA[ks]);
            mma16816(acc[1], afr, bpA[16 + ks]);
            mma16816(acc2,   afr, bfr2x[ks]);
        }
        loadB1(bpA, 2);                                // prefetch chunk 2
        #pragma unroll
        for (int ks = 0; ks < 16; ks++) {              // consume chunk 1 (h-lo)
            uint32_t afr[4];
            ldsm4(afr, &As[AS_TILE + (mt * 16 + arow) * AS_STRIDE + ks * 16 + acol]);
            mma16816(acc[0], afr, bpB[ks]);
            mma16816(acc[1], afr, bpB[16 + ks]);
        }
        #pragma unroll
        for (int ks = 0; ks < 16; ks++) {              // consume chunk 2 (h-hi)
            uint32_t afr[4];
            ldsm4(afr, &As[2 * AS_TILE + (mt * 16 + arow) * AS_STRIDE + ks * 16 + acol]);
            mma16816(acc[0], afr, bpA[ks]);
            mma16816(acc[1], afr, bpA[16 + ks]);
        }

        // Phase 1 epilogue (z / rh)
        {
            bool isZ = (jb < 512);
            #pragma unroll
            for (int nt = 0; nt < 2; nt++) {
                int col = jb + nh * 16 + nt * 8 + 2 * tig;
                float b0 = bias[col], b1 = bias[col + 1];
                #pragma unroll
                for (int half = 0; half < 2; half++) {
                    int b = mt * 16 + g + half * 8;
                    float v0 = acc[nt][half * 2 + 0];
                    float v1 = acc[nt][half * 2 + 1];
                    if (isZ) {
                        *(float2*)&g_z[b * HH + col] = make_float2(sigf(v0 + b0), sigf(v1 + b1));
                    } else {
                        int cr = col - 512;
                        float2 hv = __ldcg((const float2*)&g_h[cs][b * HH + cr]);
                        __nv_bfloat162 o;
                        o.x = __float2bfloat16(sigf(v0 + b0) * hv.x);
                        o.y = __float2bfloat16(sigf(v1 + b1) * hv.y);
                        *(__nv_bfloat162*)&g_rh[b * HH + cr] = o;
                    }
                }
            }
        }
        nbar++; gbar(nbar * GCTAS);

        // ================= Phase 2: candidate rh chunks (K=512) =================
        // B(1) prefetch overlapped with rh staging; ping-pong for chunk 2.
        const __nv_bfloat16* wrow2 = wht + (size_t)(1024 + cj0 + nh * 8 + g) * HH + 2 * tig;
        uint32_t bq[16][2];
        #pragma unroll
        for (int ks = 0; ks < 16; ks++) {
            bq[ks][0] = *(const uint32_t*)(wrow2 + ks * 16);
            bq[ks][1] = *(const uint32_t*)(wrow2 + ks * 16 + 8);
        }
        {
            const uint4* rp = (const uint4*)g_rh;
            for (int l = t; l < 4096; l += 256) {
                int half = l >> 11;
                int li = l & 2047;
                int row = li >> 5, ch = li & 31;
                *(uint4*)&As[(1 + half) * AS_TILE + row * AS_STRIDE + ch * 8] =
                    __ldcg(&rp[row * 64 + half * 32 + ch]);
            }
        }
        __syncthreads();

        uint32_t bq2[16][2];
        #pragma unroll
        for (int ks = 0; ks < 16; ks++) {
            bq2[ks][0] = *(const uint32_t*)(wrow2 + 256 + ks * 16);
            bq2[ks][1] = *(const uint32_t*)(wrow2 + 256 + ks * 16 + 8);
        }
        #pragma unroll
        for (int ks = 0; ks < 16; ks++) {              // consume rh-lo
            uint32_t afr[4];
            ldsm4(afr, &As[AS_TILE + (mt * 16 + arow) * AS_STRIDE + ks * 16 + acol]);
            mma16816(acc2, afr, bq[ks]);
        }
        #pragma unroll
        for (int ks = 0; ks < 16; ks++) {              // consume rh-hi
            uint32_t afr[4];
            ldsm4(afr, &As[2 * AS_TILE + (mt * 16 + arow) * AS_STRIDE + ks * 16 + acol]);
            mma16816(acc2, afr, bq2[ks]);
        }

        // Phase 2 epilogue: tanh + blend -> h'
        {
            int nd = cs ^ 1;
            int cj = cj0 + nh * 8 + 2 * tig;
            float b0 = bias[1024 + cj], b1 = bias[1024 + cj + 1];
            #pragma unroll
            for (int half = 0; half < 2; half++) {
                int b = mt * 16 + g + half * 8;
                float hh0 = tanhf(acc2[half * 2 + 0] + b0);
                float hh1 = tanhf(acc2[half * 2 + 1] + b1);
                float2 zv = __ldcg((const float2*)&g_z[b * HH + cj]);
                float2 hv = __ldcg((const float2*)&g_h[cs][b * HH + cj]);
                float hn0 = zv.x * hv.x + (1.0f - zv.x) * hh0;
                float hn1 = zv.y * hv.y + (1.0f - zv.y) * hh1;
                *(float2*)&g_h[nd][b * HH + cj] = make_float2(hn0, hn1);
                __nv_bfloat162 ob;
                ob.x = __float2bfloat16(hn0);
                ob.y = __float2bfloat16(hn1);
                *(__nv_bfloat162*)&g_hb[nd][b * HH + cj] = ob;
            }
        }
        nbar++; gbar(nbar * GCTAS);
        cs ^= 1;
    }
}

// -------------------- tensor-core fc (proven) --------------------
#define HS_STRIDE 264
__global__ void __launch_bounds__(256) k_fc(const float* __restrict__ fcb, int hsrc) {
    __shared__ __align__(16) __nv_bfloat16 Hs[64][HS_STRIDE];
    int t = threadIdx.x;
    int warp = t >> 5, lane = t & 31;
    int g = lane >> 2, tig = lane & 3;
    int vbase = blockIdx.x * 256 + warp * 32;

    float acc[4][4][4];
    #pragma unroll
    for (int m = 0; m < 4; m++)
        #pragma unroll
        for (int n = 0; n < 4; n++)
            { acc[m][n][0]=0.f; acc[m][n][1]=0.f; acc[m][n][2]=0.f; acc[m][n][3]=0.f; }

    int lr  = lane & 7;
    int sel = lane >> 3;
    int arow_off = lr + (sel & 1) * 8;
    int acol_off = (sel >> 1) * 8;

    for (int kh = 0; kh < 2; kh++) {
        int k0g = kh * 256;
        __syncthreads();
        for (int l = t; l < 2048; l += 256) {
            int row = l >> 5, ch = l & 31;
            const uint4* srcp = (const uint4*)(g_hb[hsrc] + row * HH + k0g);
            *(uint4*)&Hs[row][ch * 8] = srcp[ch];
        }
        __syncthreads();

        uint32_t bcur[4][2], bnxt[4][2];
        #pragma unroll
        for (int nt = 0; nt < 4; nt++) {
            const __nv_bfloat16* wr = g_wt + (size_t)(vbase + nt * 8 + g) * HH + k0g;
            bcur[nt][0] = *(const uint32_t*)(wr + 2 * tig);
            bcur[nt][1] = *(const uint32_t*)(wr + 8 + 2 * tig);
        }

        for (int ks = 0; ks < 16; ks++) {
            int kl = ks * 16;
            if (ks < 15) {
                int kn = kl + 16;
                #pragma unroll
                for (int nt = 0; nt < 4; nt++) {
                    const __nv_bfloat16* wr = g_wt + (size_t)(vbase + nt * 8 + g) * HH + k0g + kn;
                    bnxt[nt][0] = *(const uint32_t*)(wr + 2 * tig);
                    bnxt[nt][1] = *(const uint32_t*)(wr + 8 + 2 * tig);
                }
            }
            uint32_t afr[4][4];
            #pragma unroll
            for (int mt = 0; mt < 4; mt++)
                ldsm4(afr[mt], &Hs[mt * 16 + arow_off][kl + acol_off]);
            #pragma unroll
            for (int mt = 0; mt < 4; mt++)
                #pragma unroll
                for (int nt = 0; nt < 4; nt++)
                    mma16816(acc[mt][nt], afr[mt], bcur[nt]);
            if (ks < 15) {
                #pragma unroll
                for (int nt = 0; nt < 4; nt++) { bcur[nt][0] = bnxt[nt][0]; bcur[nt][1] = bnxt[nt][1]; }
            }
        }
    }

    #pragma unroll
    for (int nt = 0; nt < 4; nt++) {
        int col = vbase + nt * 8 + 2 * tig;
        float2 bv = *(const float2*)(fcb + col);
        #pragma unroll
        for (int mt = 0; mt < 4; mt++) {
            int r0 = mt * 16 + g;
            float2 o0 = make_float2(acc[mt][nt][0] + bv.x, acc[mt][nt][1] + bv.y);
            float2 o1 = make_float2(acc[mt][nt][2] + bv.x, acc[mt][nt][3] + bv.y);
            *(float2*)&g_logits[(size_t)r0 * VV + col]       = o0;
            *(float2*)&g_logits[(size_t)(r0 + 8) * VV + col] = o1;
        }
    }
}

// -------------------- per-batch loss + argmax + fused masked-mean accumulate ------------
__global__ void k_loss(const int* __restrict__ targ, int tcol, float* __restrict__ out) {
    __shared__ float sred[256];
    __shared__ float mred[256];
    __shared__ int   ired[256];
    int b = blockIdx.x, t = threadIdx.x;
    const float* lg = g_logits + (size_t)b * VV;

    float m = -3.4e38f; int mi = 0; float s1 = 0.f;
    for (int v = t; v < VV; v += 256) {
        float l = lg[v];
        s1 += expf(l);
        if (l > m) { m = l; mi = v; }
    }
    mred[t] = m; ired[t] = mi; sred[t] = s1;
    __syncthreads();
    for (int off = 128; off; off >>= 1) {
        if (t < off) {
            float mo = mred[t + off]; int io = ired[t + off];
            if (mo > mred[t] || (mo == mred[t] && io < ired[t])) { mred[t] = mo; ired[t] = io; }
            sred[t] += sred[t + off];
        }
        __syncthreads();
    }
    float inv_s1 = 1.0f / sred[0];
    int argmax = ired[0];
    __syncthreads();

    float s2 = 0.f;
    for (int v = t; v < VV; v += 256)
        s2 += expf(expf(lg[v]) * inv_s1);
    sred[t] = s2;
    __syncthreads();
    for (int off = 128; off; off >>= 1) {
        if (t < off) sred[t] += sred[t + off];
        __syncthreads();
    }
    if (t == 0) {
        int tgt = targ[b * TT + tcol];
        float pt = expf(lg[tgt]) * inv_s1;
        float ce = logf(sred[0]) - pt;
        float mask = (tgt != 0) ? 1.0f : 0.0f;
        atomicAdd(out, ce * mask * (1.0f / 64.0f));
        g_tok[b] = argmax;
    }
}

// -------------------- launch (NO device-global addresses cross this boundary) -----------
extern "C" void kernel_launch(void* const* d_in, const int* in_sizes, int n_in,
                              void* d_out, int out_size)
{
    const int*   inp     = (const int*)  d_in[0];
    const int*   targ    = (const int*)  d_in[1];
    const float* emb_enc = (const float*)d_in[2];
    const float* enc_Wx  = (const float*)d_in[3];
    const float* enc_Wh  = (const float*)d_in[4];
    const float* enc_b   = (const float*)d_in[5];
    const float* emb_dec = (const float*)d_in[6];
    const float* dec_Wx  = (const float*)d_in[7];
    const float* dec_Wh  = (const float*)d_in[8];
    const float* dec_b   = (const float*)d_in[9];
    const float* fc_W    = (const float*)d_in[10];
    const float* fc_b    = (const float*)d_in[11];
    float* out = (float*)d_out;

    cudaFuncSetAttribute(k_gru2, cudaFuncAttributeMaxDynamicSharedMemorySize, SMEM_GRU);

    k_init<<<BB, HH>>>(out);                                        // launch 1
    k_prept<<<dim3(1000, 16), 256>>>(fc_W);                         // launch 2
    k_prep_all<<<2304 + 4096, 256>>>(enc_Wx, enc_Wh, dec_Wx, dec_Wh, inp, emb_enc); // 3

    unsigned barb = 0;
    // encoder: 64 GRU steps, ONE launch                             // launch 4 <- ncu
    k_gru2<<<GCTAS, 256, SMEM_GRU>>>(nullptr, enc_b, 0, 1, 0, SS, 0, barb);
    barb += 2 * SS;

    int src = 0;   // SS even -> final encoder state in buffer 0
    for (int tt = 1; tt < TT; tt++) {
        k_gru2<<<GCTAS, 256, SMEM_GRU>>>(emb_dec, dec_b, 1, 0, src, 1, 0, barb);
        barb += 2;
        src ^= 1;
        k_fc<<<125, 256>>>(fc_b, src);
        k_loss<<<BB, 256>>>(targ, tt, out);
    }
}